// round 5
// baseline (speedup 1.0000x reference)
#include <cuda_runtime.h>
#include <cuda_bf16.h>
#include <cstdint>

#define BD 4
#define TD 50
#define DD 512
#define SRCN 400
#define SENTN 16
#define WORDN 40
#define SJ 1040
#define BT 200

// ---- unified GEMM row layout (segments padded to 128-row tiles) ----
#define MROWS 5120
#define ROW_SENT 0
#define ROW_SRC 128
#define ROW_WORD 1792
#define ROW_WQW 4352
#define ROW_WQS 4608
#define ROW_WQP 4864

// ---- scratch (device globals) ----
__device__ __nv_bfloat16 g_Ahi[MROWS * DD];
__device__ __nv_bfloat16 g_Alo[MROWS * DD];
__device__ __nv_bfloat16 g_Bhi[6 * DD * DD];   // [set][n][k] transposed weights
__device__ __nv_bfloat16 g_Blo[6 * DD * DD];
__device__ float g_act[MROWS * DD];            // all projections, fp32
__device__ float g_sent[BT * SENTN];
__device__ float g_align0[BT * SJ];
__device__ float g_align1[BT * SJ];
__device__ float g_p[BT * SJ];

__device__ __forceinline__ float tanh_fast(float x) {
    float y;
    asm("tanh.approx.f32 %0, %1;" : "=f"(y) : "f"(x));
    return y;
}

__device__ __forceinline__ uint32_t smem_u32(const void* p) {
    uint32_t a;
    asm("{ .reg .u64 t; cvta.to.shared.u64 t, %1; cvt.u32.u64 %0, t; }" : "=r"(a) : "l"(p));
    return a;
}

#define LDSM_X4(r, addr) \
    asm volatile("ldmatrix.sync.aligned.m8n8.x4.shared.b16 {%0,%1,%2,%3}, [%4];" \
        : "=r"((r)[0]), "=r"((r)[1]), "=r"((r)[2]), "=r"((r)[3]) : "r"(addr))

#define MMA_BF16(d, a, b) \
    asm volatile("mma.sync.aligned.m16n8k16.row.col.f32.bf16.bf16.f32 " \
        "{%0,%1,%2,%3}, {%4,%5,%6,%7}, {%8,%9}, {%0,%1,%2,%3};" \
        : "+f"((d)[0]), "+f"((d)[1]), "+f"((d)[2]), "+f"((d)[3]) \
        : "r"((a)[0]), "r"((a)[1]), "r"((a)[2]), "r"((a)[3]), "r"((b)[0]), "r"((b)[1]))

// ============================================================
// A conversion: gather source row, split fp32 -> bf16 hi/lo
// ============================================================
__global__ __launch_bounds__(128) void conv_a(
    const float* __restrict__ sentb, const float* __restrict__ srcb,
    const float* __restrict__ wordb, const float* __restrict__ source)
{
    int r = blockIdx.x;
    const float* p;
    if (r < ROW_SRC) {
        int q = r < 64 ? r : 63; int b = q >> 4, j = q & 15;
        p = sentb + (size_t)(j * BD + b) * DD;
    } else if (r < ROW_WORD) {
        int q = r - ROW_SRC; if (q > 1599) q = 1599;
        int b = q / SRCN, i = q - b * SRCN;
        p = srcb + (size_t)(i * BD + b) * DD;
    } else if (r < ROW_WQW) {
        int q = r - ROW_WORD; int b = q / 640, rem = q - b * 640;
        int s = rem / WORDN, w = rem - s * WORDN;
        p = wordb + (size_t)((w * BD + b) * SENTN + s) * DD;
    } else {
        int q = (r - ROW_WQW) & 255; if (q > BT - 1) q = BT - 1;
        p = source + (size_t)q * DD;
    }
    int d = threadIdx.x * 4;
    float4 x = *(const float4*)(p + d);
    __nv_bfloat16 h0 = __float2bfloat16(x.x), h1 = __float2bfloat16(x.y);
    __nv_bfloat16 h2 = __float2bfloat16(x.z), h3 = __float2bfloat16(x.w);
    __nv_bfloat16 l0 = __float2bfloat16(x.x - __bfloat162float(h0));
    __nv_bfloat16 l1 = __float2bfloat16(x.y - __bfloat162float(h1));
    __nv_bfloat16 l2 = __float2bfloat16(x.z - __bfloat162float(h2));
    __nv_bfloat16 l3 = __float2bfloat16(x.w - __bfloat162float(h3));
    size_t o = (size_t)r * DD + d;
    *(__nv_bfloat162*)&g_Ahi[o]     = __nv_bfloat162(h0, h1);
    *(__nv_bfloat162*)&g_Ahi[o + 2] = __nv_bfloat162(h2, h3);
    *(__nv_bfloat162*)&g_Alo[o]     = __nv_bfloat162(l0, l1);
    *(__nv_bfloat162*)&g_Alo[o + 2] = __nv_bfloat162(l2, l3);
}

// ============================================================
// B conversion: W[k][n] -> Bt[set][n][k], split hi/lo (64x64 smem transpose)
// ============================================================
__global__ __launch_bounds__(256) void conv_b(
    const float* __restrict__ W0, const float* __restrict__ W1, const float* __restrict__ W2,
    const float* __restrict__ W3, const float* __restrict__ W4, const float* __restrict__ W5)
{
    __shared__ float tile[64][65];
    int set = blockIdx.z;
    const float* W = (set == 0) ? W0 : (set == 1) ? W1 : (set == 2) ? W2 :
                     (set == 3) ? W3 : (set == 4) ? W4 : W5;
    int k0 = blockIdx.x * 64, n0 = blockIdx.y * 64;
    int tid = threadIdx.x;
    int rr = tid >> 4, c4 = (tid & 15) << 2;
#pragma unroll
    for (int it = 0; it < 4; it++) {
        int r = rr + it * 16;
        float4 v = *(const float4*)&W[(size_t)(k0 + r) * DD + n0 + c4];
        tile[r][c4] = v.x; tile[r][c4 + 1] = v.y; tile[r][c4 + 2] = v.z; tile[r][c4 + 3] = v.w;
    }
    __syncthreads();
    size_t obase = (size_t)set * DD * DD;
#pragma unroll
    for (int it = 0; it < 4; it++) {
        int n = rr + it * 16;
        float x0 = tile[c4][n], x1 = tile[c4 + 1][n], x2 = tile[c4 + 2][n], x3 = tile[c4 + 3][n];
        __nv_bfloat16 h0 = __float2bfloat16(x0), h1 = __float2bfloat16(x1);
        __nv_bfloat16 h2 = __float2bfloat16(x2), h3 = __float2bfloat16(x3);
        __nv_bfloat16 l0 = __float2bfloat16(x0 - __bfloat162float(h0));
        __nv_bfloat16 l1 = __float2bfloat16(x1 - __bfloat162float(h1));
        __nv_bfloat16 l2 = __float2bfloat16(x2 - __bfloat162float(h2));
        __nv_bfloat16 l3 = __float2bfloat16(x3 - __bfloat162float(h3));
        size_t o = obase + (size_t)(n0 + n) * DD + k0 + c4;
        *(__nv_bfloat162*)&g_Bhi[o]     = __nv_bfloat162(h0, h1);
        *(__nv_bfloat162*)&g_Bhi[o + 2] = __nv_bfloat162(h2, h3);
        *(__nv_bfloat162*)&g_Blo[o]     = __nv_bfloat162(l0, l1);
        *(__nv_bfloat162*)&g_Blo[o + 2] = __nv_bfloat162(l2, l3);
    }
}

// ============================================================
// warp-MMA split-bf16 GEMM: g_act = A @ B^T (+bias on wq segs)
// CTA 128x128, 8 warps (4M x 2N), warp tile 32x64, K-chunk 64
// smem: Ahi 0 | Alo 16K | Bhi 32K | Blo 48K   (64 KB dynamic)
// ============================================================
#define SMEM_GEMM 65536
__global__ __launch_bounds__(256, 1) void mma_gemm(
    const float* __restrict__ bqw, const float* __restrict__ bqs, const float* __restrict__ bqp)
{
    extern __shared__ __align__(16) char sm[];
    uint32_t sb = smem_u32(sm);
    int tid = threadIdx.x, wid = tid >> 5, lane = tid & 31;
    int m0 = blockIdx.x * 128, n0 = blockIdx.y * 128;
    int seg = (m0 < ROW_SRC) ? 0 : (m0 < ROW_WORD) ? 1 : (m0 < ROW_WQW) ? 2 :
              (m0 < ROW_WQS) ? 3 : (m0 < ROW_WQP) ? 4 : 5;

    const __nv_bfloat16* Ah = g_Ahi + (size_t)m0 * DD;
    const __nv_bfloat16* Al = g_Alo + (size_t)m0 * DD;
    const __nv_bfloat16* Bh = g_Bhi + (size_t)seg * DD * DD + (size_t)n0 * DD;
    const __nv_bfloat16* Bl = g_Blo + (size_t)seg * DD * DD + (size_t)n0 * DD;

    int wm0 = (wid >> 1) * 32;     // warp M offset (0..96)
    int wn0 = (wid & 1) * 64;      // warp N offset (0/64)

    float acc[2][8][4] = {};

    for (int kc = 0; kc < 8; kc++) {
        int k0 = kc * 64;
        __syncthreads();
        // stage 4 tiles (each 128 rows x 64 cols bf16 = 16 KB), 16B-swizzled
        for (int i = tid; i < 1024; i += 256) {
            int r = i >> 3, c = i & 7;
            uint32_t off = (uint32_t)(r << 7) + (uint32_t)((c ^ (r & 7)) << 4);
            *(uint4*)(sm + off)         = *(const uint4*)(Ah + (size_t)r * DD + k0 + c * 8);
            *(uint4*)(sm + 16384 + off) = *(const uint4*)(Al + (size_t)r * DD + k0 + c * 8);
            *(uint4*)(sm + 32768 + off) = *(const uint4*)(Bh + (size_t)r * DD + k0 + c * 8);
            *(uint4*)(sm + 49152 + off) = *(const uint4*)(Bl + (size_t)r * DD + k0 + c * 8);
        }
        __syncthreads();
#pragma unroll
        for (int ks = 0; ks < 4; ks++) {
            uint32_t ah[2][4], al[2][4];
#pragma unroll
            for (int mt = 0; mt < 2; mt++) {
                int mrow = wm0 + mt * 16 + (lane & 15);
                int cc = ks * 2 + (lane >> 4);
                uint32_t a_off = (uint32_t)(mrow << 7) + (uint32_t)((cc ^ (mrow & 7)) << 4);
                LDSM_X4(ah[mt], sb + a_off);
                LDSM_X4(al[mt], sb + 16384 + a_off);
            }
            uint32_t bh[4][4], bl[4][4];
#pragma unroll
            for (int np = 0; np < 4; np++) {
                int nrow = wn0 + np * 16 + ((lane >> 4) << 3) + (lane & 7);
                int cc = ks * 2 + ((lane >> 3) & 1);
                uint32_t b_off = (uint32_t)(nrow << 7) + (uint32_t)((cc ^ (nrow & 7)) << 4);
                LDSM_X4(bh[np], sb + 32768 + b_off);
                LDSM_X4(bl[np], sb + 49152 + b_off);
            }
#pragma unroll
            for (int mt = 0; mt < 2; mt++) {
#pragma unroll
                for (int nt = 0; nt < 8; nt++) {
                    uint32_t* pbh = &bh[nt >> 1][(nt & 1) * 2];
                    uint32_t* pbl = &bl[nt >> 1][(nt & 1) * 2];
                    MMA_BF16(acc[mt][nt], ah[mt], pbh);
                    MMA_BF16(acc[mt][nt], ah[mt], pbl);
                    MMA_BF16(acc[mt][nt], al[mt], pbh);
                }
            }
        }
    }

    // epilogue
    const float* bias = (seg == 3) ? bqw : (seg == 4) ? bqs : (seg == 5) ? bqp : (const float*)0;
#pragma unroll
    for (int mt = 0; mt < 2; mt++) {
#pragma unroll
        for (int nt = 0; nt < 8; nt++) {
            int m = m0 + wm0 + mt * 16 + (lane >> 2);
            int n = n0 + wn0 + nt * 8 + (lane & 3) * 2;
            float2 v0 = make_float2(acc[mt][nt][0], acc[mt][nt][1]);
            float2 v1 = make_float2(acc[mt][nt][2], acc[mt][nt][3]);
            if (bias) {
                float b0 = bias[n], b1 = bias[n + 1];
                v0.x += b0; v0.y += b1; v1.x += b0; v1.y += b1;
            }
            *(float2*)&g_act[(size_t)m * DD + n] = v0;
            *(float2*)&g_act[(size_t)(m + 8) * DD + n] = v1;
        }
    }
}

// ============================================================
// sentence-level scores
// ============================================================
__global__ __launch_bounds__(128) void sent_kernel(const float* __restrict__ v_sent)
{
    int row = blockIdx.x;
    int b = row / TD;
    int lane = threadIdx.x & 31, warp = threadIdx.x >> 5;
    const float* wq = g_act + (size_t)(ROW_WQS + row) * DD;
#pragma unroll
    for (int jj = 0; jj < 4; jj++) {
        int j = warp * 4 + jj;
        const float* uh = g_act + (size_t)(b * 16 + j) * DD;
        float acc = 0.f;
        for (int d = lane; d < DD; d += 32)
            acc += v_sent[d] * tanh_fast(wq[d] + uh[d]);
#pragma unroll
        for (int o = 16; o; o >>= 1) acc += __shfl_xor_sync(0xffffffffu, acc, o);
        if (lane == 0) g_sent[row * SENTN + j] = acc;
    }
}

// ============================================================
// main score kernel (raw partial scores, d split in halves)
// ============================================================
#define SC_CHUNK 64
#define SC_STRIDE 68
__global__ __launch_bounds__(256) void score_kernel(
    const float* __restrict__ v_pass, const float* __restrict__ v_word)
{
    __shared__ float wq_s[16 * SC_STRIDE];
    __shared__ float uh_s[80 * SC_STRIDE];
    __shared__ float v_s[SC_CHUNK];
    int tid = threadIdx.x;
    int jt = blockIdx.x, tt = blockIdx.y;
    int b = blockIdx.z & 3, half = blockIdx.z >> 2;
    int t0 = tt * 16;
    bool is_src = (jt < 5);
    const float* wqb = g_act + (size_t)((is_src ? ROW_WQP : ROW_WQW) + b * TD) * DD;
    int uh0 = is_src ? (ROW_SRC + b * SRCN + jt * 80) : (ROW_WORD + b * 640 + (jt - 5) * 80);
    const float* v = is_src ? v_pass : v_word;
    int d_base = half * 256;

    int tx = tid & 15, ty = tid >> 4;
    float acc[5] = {0.f, 0.f, 0.f, 0.f, 0.f};

    for (int c = 0; c < 4; c++) {
        int d0 = d_base + c * SC_CHUNK;
        __syncthreads();
        {
            int r = tid >> 4, col = (tid & 15) << 2;
            *(float4*)&wq_s[r * SC_STRIDE + col] =
                *(const float4*)&wqb[(size_t)(t0 + r) * DD + d0 + col];
        }
        for (int i = tid; i < 80 * 16; i += 256) {
            int r = i >> 4, col = (i & 15) << 2;
            *(float4*)&uh_s[r * SC_STRIDE + col] =
                *(const float4*)&g_act[(size_t)(uh0 + r) * DD + d0 + col];
        }
        if (tid < SC_CHUNK) v_s[tid] = v[d0 + tid];
        __syncthreads();
#pragma unroll 4
        for (int d4 = 0; d4 < 16; d4++) {
            float4 w4 = *(const float4*)&wq_s[ty * SC_STRIDE + (d4 << 2)];
            float4 v4 = *(const float4*)&v_s[d4 << 2];
#pragma unroll
            for (int u = 0; u < 5; u++) {
                float4 u4 = *(const float4*)&uh_s[(tx + 16 * u) * SC_STRIDE + (d4 << 2)];
                acc[u] += v4.x * tanh_fast(w4.x + u4.x);
                acc[u] += v4.y * tanh_fast(w4.y + u4.y);
                acc[u] += v4.z * tanh_fast(w4.z + u4.z);
                acc[u] += v4.w * tanh_fast(w4.w + u4.w);
            }
        }
    }

    int t = t0 + ty;
    if (t < TD) {
        float* arow = (half ? g_align1 : g_align0) + (size_t)(b * TD + t) * SJ;
        int jcol0 = is_src ? jt * 80 : SRCN + (jt - 5) * 80;
#pragma unroll
        for (int u = 0; u < 5; u++)
            arow[jcol0 + tx + 16 * u] = acc[u];
    }
}

// ============================================================
// softmax: combine halves, hier multiply, mask, softmax
// ============================================================
__global__ __launch_bounds__(256) void softmax_kernel(
    const int* __restrict__ src_len, const int* __restrict__ word_len)
{
    __shared__ float sval[SJ];
    __shared__ float red[256];
    __shared__ float sents[SENTN];
    int row = blockIdx.x, tid = threadIdx.x;
    int b = row / TD;
    if (tid < SENTN) sents[tid] = g_sent[row * SENTN + tid];
    __syncthreads();
    int sl = src_len[b];
    for (int j = tid; j < SJ; j += 256) {
        float rv = g_align0[(size_t)row * SJ + j] + g_align1[(size_t)row * SJ + j];
        float val;
        if (j < SRCN) {
            val = (j < sl) ? rv : -1e30f;
        } else {
            int jw = j - SRCN; int s = jw / WORDN, w = jw - s * WORDN;
            val = (w < word_len[b * SENTN + s]) ? rv * sents[s] : -1e30f;
        }
        sval[j] = val;
    }
    __syncthreads();
    float m = -3.4e38f;
    for (int j = tid; j < SJ; j += 256) m = fmaxf(m, sval[j]);
    red[tid] = m; __syncthreads();
    for (int o = 128; o; o >>= 1) { if (tid < o) red[tid] = fmaxf(red[tid], red[tid + o]); __syncthreads(); }
    m = red[0]; __syncthreads();
    float s = 0.f;
    for (int j = tid; j < SJ; j += 256) { float e = __expf(sval[j] - m); sval[j] = e; s += e; }
    red[tid] = s; __syncthreads();
    for (int o = 128; o; o >>= 1) { if (tid < o) red[tid] += red[tid + o]; __syncthreads(); }
    float inv = 1.0f / red[0];
    for (int j = tid; j < SJ; j += 256) g_p[(size_t)row * SJ + j] = sval[j] * inv;
}

// ============================================================
// context: c[b,t,d] = sum_j p[b,t,j] * mem[b,j,d]
// ============================================================
__global__ __launch_bounds__(256) void context_kernel(
    const float* __restrict__ srcb, const float* __restrict__ wordb, float* __restrict__ out)
{
    __shared__ float p_s[50 * 80];
    __shared__ float m_s[80 * 33];
    int tid = threadIdx.x;
    int b = blockIdx.y;
    int d0 = blockIdx.x * 32;
    int tx = tid & 31, ty = tid >> 5;
    float acc[7] = {};

    for (int j0 = 0; j0 < SJ; j0 += 80) {
        __syncthreads();
        for (int i = tid; i < 50 * 80; i += 256) {
            int r = i / 80, c = i - r * 80;
            p_s[i] = g_p[(size_t)(b * TD + r) * SJ + j0 + c];
        }
        for (int i = tid; i < 80 * 32; i += 256) {
            int r = i >> 5, c = i & 31;
            int j = j0 + r;
            const float* mp;
            if (j < SRCN) mp = srcb + (size_t)(j * BD + b) * DD;
            else { int jw = j - SRCN; int s = jw / WORDN, w = jw - s * WORDN;
                   mp = wordb + (size_t)((w * BD + b) * SENTN + s) * DD; }
            m_s[r * 33 + c] = mp[d0 + c];
        }
        __syncthreads();
        for (int j = 0; j < 80; j++) {
            float mv = m_s[j * 33 + tx];
#pragma unroll
            for (int q = 0; q < 7; q++) {
                int t = ty + (q << 3);
                if (t < TD) acc[q] += p_s[t * 80 + j] * mv;
            }
        }
    }
#pragma unroll
    for (int q = 0; q < 7; q++) {
        int t = ty + (q << 3);
        if (t < TD) out[(size_t)(b * TD + t) * DD + d0 + tx] = acc[q];
    }
}

// ============================================================
extern "C" void kernel_launch(void* const* d_in, const int* in_sizes, int n_in,
                              void* d_out, int out_size)
{
    const float* source    = (const float*)d_in[0];
    const float* src_bank  = (const float*)d_in[1];
    const int*   src_len   = (const int*)  d_in[2];
    const float* sent_bank = (const float*)d_in[3];
    const float* word_bank = (const float*)d_in[5];
    const int*   word_len  = (const int*)  d_in[6];
    const float* Wq_word = (const float*)d_in[7];
    const float* bq_word = (const float*)d_in[8];
    const float* Uc_word = (const float*)d_in[9];
    const float* v_word  = (const float*)d_in[10];
    const float* Wq_sent = (const float*)d_in[11];
    const float* bq_sent = (const float*)d_in[12];
    const float* Uc_sent = (const float*)d_in[13];
    const float* v_sent  = (const float*)d_in[14];
    const float* Wq_pass = (const float*)d_in[15];
    const float* bq_pass = (const float*)d_in[16];
    const float* Uc_pass = (const float*)d_in[17];
    const float* v_pass  = (const float*)d_in[18];
    float* out = (float*)d_out;

    cudaFuncSetAttribute(mma_gemm, cudaFuncAttributeMaxDynamicSharedMemorySize, SMEM_GEMM);

    conv_a<<<MROWS, 128>>>(sent_bank, src_bank, word_bank, source);
    conv_b<<<dim3(8, 8, 6), 256>>>(Uc_sent, Uc_pass, Uc_word, Wq_word, Wq_sent, Wq_pass);
    mma_gemm<<<dim3(40, 4), 256, SMEM_GEMM>>>(bq_word, bq_sent, bq_pass);
    sent_kernel<<<200, 128>>>(v_sent);
    score_kernel<<<dim3(13, 4, 8), 256>>>(v_pass, v_word);
    softmax_kernel<<<200, 256>>>(src_len, word_len);
    context_kernel<<<dim3(16, 4), 256>>>(src_bank, word_bank, out);
}

// round 7
// speedup vs baseline: 1.2082x; 1.2082x over previous
#include <cuda_runtime.h>
#include <cstdint>

#define BD 4
#define TD 50
#define DD 512
#define SRCN 400
#define SENTN 16
#define WORDN 40
#define SJ 1040
#define BT 200

// ---- unified GEMM row layout (segments padded to 64-row tiles) ----
#define MROWS 5120
#define ROW_SENT 0
#define ROW_SRC 128
#define ROW_WORD 1792
#define ROW_WQW 4352
#define ROW_WQS 4608
#define ROW_WQP 4864

// ---- scratch (device globals) ----
__device__ float g_act[MROWS * DD];            // all projections, fp32
__device__ float g_sent[BT * SENTN];
__device__ float g_align0[BT * SJ];
__device__ float g_align1[BT * SJ];
__device__ float g_p[BT * SJ];

__device__ __forceinline__ float tanh_fast(float x) {
    float y;
    asm("tanh.approx.f32 %0, %1;" : "=f"(y) : "f"(x));
    return y;
}

// ---- packed f32x2 ops (base sm_100-family PTX; NOT an 'a' feature) ----
#define FFMA2(acc, a, b) \
    asm("fma.rn.f32x2 %0, %1, %2, %0;" : "+l"(acc) : "l"(a), "l"(b))
#define PACK2(d, lo, hi) \
    asm("mov.b64 %0, {%1, %2};" : "=l"(d) : "r"(__float_as_uint(lo)), "r"(__float_as_uint(hi)))
#define UNPACK2(lo, hi, v) \
    asm("mov.b64 {%0, %1}, %2;" : "=r"(lo), "=r"(hi) : "l"(v))

// ============================================================
// unified FFMA2 GEMM: g_act[M=5120][512] = gather(A) @ W_seg (+bias)
// CTA tile 64(M) x 128(N), 64 threads, per-thread 16x8 (M-paired f32x2)
// K-chunk 32, 16 chunks. grid (80, 4).
// ============================================================
__global__ __launch_bounds__(64) void ffma2_gemm(
    const float* __restrict__ sentb, const float* __restrict__ srcb,
    const float* __restrict__ wordb, const float* __restrict__ source,
    const float* __restrict__ U0, const float* __restrict__ U1, const float* __restrict__ U2,
    const float* __restrict__ W3, const float* __restrict__ W4, const float* __restrict__ W5,
    const float* __restrict__ bqw, const float* __restrict__ bqs, const float* __restrict__ bqp)
{
    __shared__ float As[32][64];          // [k][m]
    __shared__ float Bs[32][128];         // [k][n]
    __shared__ const float* rowp[64];

    int tid = threadIdx.x;
    int m0 = blockIdx.x * 64, n0 = blockIdx.y * 128;
    int seg = (m0 < ROW_SRC) ? 0 : (m0 < ROW_WORD) ? 1 : (m0 < ROW_WQW) ? 2 :
              (m0 < ROW_WQS) ? 3 : (m0 < ROW_WQP) ? 4 : 5;
    const float* W = (seg == 0) ? U0 : (seg == 1) ? U1 : (seg == 2) ? U2 :
                     (seg == 3) ? W3 : (seg == 4) ? W4 : W5;

    // row-pointer table for the gathered A tile
    {
        int r = m0 + tid;
        const float* p;
        if (r < ROW_SRC) {
            int q = r < 64 ? r : 63; int b = q >> 4, j = q & 15;
            p = sentb + (size_t)(j * BD + b) * DD;
        } else if (r < ROW_WORD) {
            int q = r - ROW_SRC; if (q > 1599) q = 1599;
            int b = q / SRCN, i = q - b * SRCN;
            p = srcb + (size_t)(i * BD + b) * DD;
        } else if (r < ROW_WQW) {
            int q = r - ROW_WORD; int b = q / 640, rem = q - b * 640;
            int s = rem / WORDN, w = rem - s * WORDN;
            p = wordb + (size_t)((w * BD + b) * SENTN + s) * DD;
        } else {
            int q = (r - ROW_WQW) & 255; if (q > BT - 1) q = BT - 1;
            p = source + (size_t)q * DD;
        }
        rowp[tid] = p;
    }

    int mb = (tid & 3) * 16;      // thread M base (0..48)
    int nb = (tid >> 2) * 8;      // thread N base (0..120)

    unsigned long long acc[8][8];
#pragma unroll
    for (int i = 0; i < 8; i++)
#pragma unroll
        for (int j = 0; j < 8; j++) acc[i][j] = 0ull;

    for (int kc = 0; kc < 16; kc++) {
        int k0 = kc * 32;
        __syncthreads();
        // stage A (64 rows x 32 k), transposed into As[k][m]
#pragma unroll
        for (int s = 0; s < 8; s++) {
            int g = tid + s * 64;          // 512 float4-granules
            int m = g & 63, kg = g >> 6;   // kg 0..7
            float4 v = *(const float4*)(rowp[m] + k0 + kg * 4);
            As[kg * 4 + 0][m] = v.x;
            As[kg * 4 + 1][m] = v.y;
            As[kg * 4 + 2][m] = v.z;
            As[kg * 4 + 3][m] = v.w;
        }
        // stage B (32 k x 128 n) natural
#pragma unroll
        for (int s = 0; s < 16; s++) {
            int g = tid + s * 64;          // 1024 float4-granules
            int k = g >> 5, n4 = (g & 31) * 4;
            *(float4*)&Bs[k][n4] = *(const float4*)&W[(size_t)(k0 + k) * DD + n0 + n4];
        }
        __syncthreads();

#pragma unroll 4
        for (int k = 0; k < 32; k++) {
            // A fragment: 8 natural M-pairs
            ulonglong2 a01 = *(const ulonglong2*)&As[k][mb];
            ulonglong2 a23 = *(const ulonglong2*)&As[k][mb + 4];
            ulonglong2 a45 = *(const ulonglong2*)&As[k][mb + 8];
            ulonglong2 a67 = *(const ulonglong2*)&As[k][mb + 12];
            unsigned long long a2[8] = {a01.x, a01.y, a23.x, a23.y, a45.x, a45.y, a67.x, a67.y};
            // B fragment: 8 scalars, duplicated into pairs
            float4 b0 = *(const float4*)&Bs[k][nb];
            float4 b1 = *(const float4*)&Bs[k][nb + 4];
            unsigned long long bd[8];
            PACK2(bd[0], b0.x, b0.x); PACK2(bd[1], b0.y, b0.y);
            PACK2(bd[2], b0.z, b0.z); PACK2(bd[3], b0.w, b0.w);
            PACK2(bd[4], b1.x, b1.x); PACK2(bd[5], b1.y, b1.y);
            PACK2(bd[6], b1.z, b1.z); PACK2(bd[7], b1.w, b1.w);
#pragma unroll
            for (int mp = 0; mp < 8; mp++)
#pragma unroll
                for (int j = 0; j < 8; j++)
                    FFMA2(acc[mp][j], a2[mp], bd[j]);
        }
    }

    // epilogue: unpack pairs, add bias on wq segments
    const float* bias = (seg == 3) ? bqw : (seg == 4) ? bqs : (seg == 5) ? bqp : (const float*)0;
    float bb[8];
#pragma unroll
    for (int j = 0; j < 8; j++) bb[j] = bias ? bias[n0 + nb + j] : 0.0f;

#pragma unroll
    for (int mp = 0; mp < 8; mp++) {
        float lo[8], hi[8];
#pragma unroll
        for (int j = 0; j < 8; j++) {
            uint32_t l, h;
            UNPACK2(l, h, acc[mp][j]);
            lo[j] = __uint_as_float(l) + bb[j];
            hi[j] = __uint_as_float(h) + bb[j];
        }
        size_t r0 = (size_t)(m0 + mb + 2 * mp) * DD + n0 + nb;
        *(float4*)&g_act[r0]         = make_float4(lo[0], lo[1], lo[2], lo[3]);
        *(float4*)&g_act[r0 + 4]     = make_float4(lo[4], lo[5], lo[6], lo[7]);
        *(float4*)&g_act[r0 + DD]     = make_float4(hi[0], hi[1], hi[2], hi[3]);
        *(float4*)&g_act[r0 + DD + 4] = make_float4(hi[4], hi[5], hi[6], hi[7]);
    }
}

// ============================================================
// sentence-level scores: one warp per j, wq row staged in smem
// ============================================================
__global__ __launch_bounds__(512) void sent_kernel(const float* __restrict__ v_sent)
{
    __shared__ float wq_s[DD];
    __shared__ float vs[DD];
    int row = blockIdx.x;          // b*50 + t
    int b = row / TD;
    int tid = threadIdx.x, lane = tid & 31, w = tid >> 5;   // 16 warps = 16 j
    wq_s[tid] = g_act[(size_t)(ROW_WQS + row) * DD + tid];
    vs[tid] = v_sent[tid];
    __syncthreads();
    const float* uh = g_act + (size_t)(b * 16 + w) * DD;
    float acc = 0.f;
#pragma unroll
    for (int it = 0; it < 4; it++) {
        int d = it * 128 + lane * 4;
        float4 u = *(const float4*)&uh[d];
        acc += vs[d + 0] * tanh_fast(wq_s[d + 0] + u.x);
        acc += vs[d + 1] * tanh_fast(wq_s[d + 1] + u.y);
        acc += vs[d + 2] * tanh_fast(wq_s[d + 2] + u.z);
        acc += vs[d + 3] * tanh_fast(wq_s[d + 3] + u.w);
    }
#pragma unroll
    for (int o = 16; o; o >>= 1) acc += __shfl_xor_sync(0xffffffffu, acc, o);
    if (lane == 0) g_sent[row * SENTN + w] = acc;
}

// ============================================================
// main score kernel (raw partial scores, d split in halves)
// ============================================================
#define SC_CHUNK 64
#define SC_STRIDE 68
__global__ __launch_bounds__(256) void score_kernel(
    const float* __restrict__ v_pass, const float* __restrict__ v_word)
{
    __shared__ float wq_s[16 * SC_STRIDE];
    __shared__ float uh_s[80 * SC_STRIDE];
    __shared__ float v_s[SC_CHUNK];
    int tid = threadIdx.x;
    int jt = blockIdx.x, tt = blockIdx.y;
    int b = blockIdx.z & 3, half = blockIdx.z >> 2;
    int t0 = tt * 16;
    bool is_src = (jt < 5);
    const float* wqb = g_act + (size_t)((is_src ? ROW_WQP : ROW_WQW) + b * TD) * DD;
    int uh0 = is_src ? (ROW_SRC + b * SRCN + jt * 80) : (ROW_WORD + b * 640 + (jt - 5) * 80);
    const float* v = is_src ? v_pass : v_word;
    int d_base = half * 256;

    int tx = tid & 15, ty = tid >> 4;
    float acc[5] = {0.f, 0.f, 0.f, 0.f, 0.f};

    for (int c = 0; c < 4; c++) {
        int d0 = d_base + c * SC_CHUNK;
        __syncthreads();
        {
            int r = tid >> 4, col = (tid & 15) << 2;
            *(float4*)&wq_s[r * SC_STRIDE + col] =
                *(const float4*)&wqb[(size_t)(t0 + r) * DD + d0 + col];
        }
        for (int i = tid; i < 80 * 16; i += 256) {
            int r = i >> 4, col = (i & 15) << 2;
            *(float4*)&uh_s[r * SC_STRIDE + col] =
                *(const float4*)&g_act[(size_t)(uh0 + r) * DD + d0 + col];
        }
        if (tid < SC_CHUNK) v_s[tid] = v[d0 + tid];
        __syncthreads();
#pragma unroll 4
        for (int d4 = 0; d4 < 16; d4++) {
            float4 w4 = *(const float4*)&wq_s[ty * SC_STRIDE + (d4 << 2)];
            float4 v4 = *(const float4*)&v_s[d4 << 2];
#pragma unroll
            for (int u = 0; u < 5; u++) {
                float4 u4 = *(const float4*)&uh_s[(tx + 16 * u) * SC_STRIDE + (d4 << 2)];
                acc[u] += v4.x * tanh_fast(w4.x + u4.x);
                acc[u] += v4.y * tanh_fast(w4.y + u4.y);
                acc[u] += v4.z * tanh_fast(w4.z + u4.z);
                acc[u] += v4.w * tanh_fast(w4.w + u4.w);
            }
        }
    }

    int t = t0 + ty;
    if (t < TD) {
        float* arow = (half ? g_align1 : g_align0) + (size_t)(b * TD + t) * SJ;
        int jcol0 = is_src ? jt * 80 : SRCN + (jt - 5) * 80;
#pragma unroll
        for (int u = 0; u < 5; u++)
            arow[jcol0 + tx + 16 * u] = acc[u];
    }
}

// ============================================================
// softmax: combine halves, hier multiply, mask, softmax
// ============================================================
__global__ __launch_bounds__(256) void softmax_kernel(
    const int* __restrict__ src_len, const int* __restrict__ word_len)
{
    __shared__ float sval[SJ];
    __shared__ float red[256];
    __shared__ float sents[SENTN];
    int row = blockIdx.x, tid = threadIdx.x;
    int b = row / TD;
    if (tid < SENTN) sents[tid] = g_sent[row * SENTN + tid];
    __syncthreads();
    int sl = src_len[b];
    for (int j = tid; j < SJ; j += 256) {
        float rv = g_align0[(size_t)row * SJ + j] + g_align1[(size_t)row * SJ + j];
        float val;
        if (j < SRCN) {
            val = (j < sl) ? rv : -1e30f;
        } else {
            int jw = j - SRCN; int s = jw / WORDN, w = jw - s * WORDN;
            val = (w < word_len[b * SENTN + s]) ? rv * sents[s] : -1e30f;
        }
        sval[j] = val;
    }
    __syncthreads();
    float m = -3.4e38f;
    for (int j = tid; j < SJ; j += 256) m = fmaxf(m, sval[j]);
    red[tid] = m; __syncthreads();
    for (int o = 128; o; o >>= 1) { if (tid < o) red[tid] = fmaxf(red[tid], red[tid + o]); __syncthreads(); }
    m = red[0]; __syncthreads();
    float s = 0.f;
    for (int j = tid; j < SJ; j += 256) { float e = __expf(sval[j] - m); sval[j] = e; s += e; }
    red[tid] = s; __syncthreads();
    for (int o = 128; o; o >>= 1) { if (tid < o) red[tid] += red[tid + o]; __syncthreads(); }
    float inv = 1.0f / red[0];
    for (int j = tid; j < SJ; j += 256) g_p[(size_t)row * SJ + j] = sval[j] * inv;
}

// ============================================================
// context: c[b,t,d] = sum_j p[b,t,j] * mem[b,j,d]
// ============================================================
__global__ __launch_bounds__(256) void context_kernel(
    const float* __restrict__ srcb, const float* __restrict__ wordb, float* __restrict__ out)
{
    __shared__ float p_s[50 * 80];
    __shared__ float m_s[80 * 33];
    int tid = threadIdx.x;
    int b = blockIdx.y;
    int d0 = blockIdx.x * 32;
    int tx = tid & 31, ty = tid >> 5;
    float acc[7] = {};

    for (int j0 = 0; j0 < SJ; j0 += 80) {
        __syncthreads();
        for (int i = tid; i < 50 * 80; i += 256) {
            int r = i / 80, c = i - r * 80;
            p_s[i] = g_p[(size_t)(b * TD + r) * SJ + j0 + c];
        }
        for (int i = tid; i < 80 * 32; i += 256) {
            int r = i >> 5, c = i & 31;
            int j = j0 + r;
            const float* mp;
            if (j < SRCN) mp = srcb + (size_t)(j * BD + b) * DD;
            else { int jw = j - SRCN; int s = jw / WORDN, w = jw - s * WORDN;
                   mp = wordb + (size_t)((w * BD + b) * SENTN + s) * DD; }
            m_s[r * 33 + c] = mp[d0 + c];
        }
        __syncthreads();
        for (int j = 0; j < 80; j++) {
            float mv = m_s[j * 33 + tx];
#pragma unroll
            for (int q = 0; q < 7; q++) {
                int t = ty + (q << 3);
                if (t < TD) acc[q] += p_s[t * 80 + j] * mv;
            }
        }
    }
#pragma unroll
    for (int q = 0; q < 7; q++) {
        int t = ty + (q << 3);
        if (t < TD) out[(size_t)(b * TD + t) * DD + d0 + tx] = acc[q];
    }
}

// ============================================================
extern "C" void kernel_launch(void* const* d_in, const int* in_sizes, int n_in,
                              void* d_out, int out_size)
{
    const float* source    = (const float*)d_in[0];
    const float* src_bank  = (const float*)d_in[1];
    const int*   src_len   = (const int*)  d_in[2];
    const float* sent_bank = (const float*)d_in[3];
    const float* word_bank = (const float*)d_in[5];
    const int*   word_len  = (const int*)  d_in[6];
    const float* Wq_word = (const float*)d_in[7];
    const float* bq_word = (const float*)d_in[8];
    const float* Uc_word = (const float*)d_in[9];
    const float* v_word  = (const float*)d_in[10];
    const float* Wq_sent = (const float*)d_in[11];
    const float* bq_sent = (const float*)d_in[12];
    const float* Uc_sent = (const float*)d_in[13];
    const float* v_sent  = (const float*)d_in[14];
    const float* Wq_pass = (const float*)d_in[15];
    const float* bq_pass = (const float*)d_in[16];
    const float* Uc_pass = (const float*)d_in[17];
    const float* v_pass  = (const float*)d_in[18];
    float* out = (float*)d_out;

    ffma2_gemm<<<dim3(80, 4), 64>>>(
        sent_bank, src_bank, word_bank, source,
        Uc_sent, Uc_pass, Uc_word, Wq_word, Wq_sent, Wq_pass,
        bq_word, bq_sent, bq_pass);
    sent_kernel<<<200, 512>>>(v_sent);
    score_kernel<<<dim3(13, 4, 8), 256>>>(v_pass, v_word);
    softmax_kernel<<<200, 256>>>(src_len, word_len);
    context_kernel<<<dim3(16, 4), 256>>>(src_bank, word_bank, out);
}

// round 8
// speedup vs baseline: 1.2821x; 1.0612x over previous
#include <cuda_runtime.h>
#include <cstdint>

#define BD 4
#define TD 50
#define DD 512
#define SRCN 400
#define SENTN 16
#define WORDN 40
#define SJ 1040
#define BT 200

// ---- unified GEMM row layout (segments padded to 128-row tiles) ----
#define MROWS 5120
#define ROW_SENT 0
#define ROW_SRC 128
#define ROW_WORD 1792
#define ROW_WQW 4352
#define ROW_WQS 4608
#define ROW_WQP 4864

// ---- scratch (device globals) ----
__device__ float g_act0[MROWS * DD];           // K-half 0 partial (+bias)
__device__ float g_act1[MROWS * DD];           // K-half 1 partial
__device__ float g_act[MROWS * DD];            // combined projections
__device__ float g_sent[BT * SENTN];
__device__ float g_align0[BT * SJ];
__device__ float g_align1[BT * SJ];
__device__ float g_p[BT * SJ];

__device__ __forceinline__ float tanh_fast(float x) {
    float y;
    asm("tanh.approx.f32 %0, %1;" : "=f"(y) : "f"(x));
    return y;
}

// ---- packed f32x2 ops ----
#define FFMA2(acc, a, b) \
    asm("fma.rn.f32x2 %0, %1, %2, %0;" : "+l"(acc) : "l"(a), "l"(b))
#define PACK2(d, lo, hi) \
    asm("mov.b64 %0, {%1, %2};" : "=l"(d) : "r"(__float_as_uint(lo)), "r"(__float_as_uint(hi)))
#define UNPACK2(lo, hi, v) \
    asm("mov.b64 {%0, %1}, %2;" : "=r"(lo), "=r"(hi) : "l"(v))

// ============================================================
// unified FFMA2 GEMM, K-split: g_act{0,1}[5120][512] = gather(A) @ W_seg
// CTA tile 128(M) x 128(N) x 256(K-half); 128 threads, per-thread 16x8.
// grid (40, 4, 2).
// A fragment: 4 chunks of 4 floats at (tid&7)*4 + 32i  (bank-conflict-free)
// ============================================================
__global__ __launch_bounds__(128) void ffma2_gemm(
    const float* __restrict__ sentb, const float* __restrict__ srcb,
    const float* __restrict__ wordb, const float* __restrict__ source,
    const float* __restrict__ U0, const float* __restrict__ U1, const float* __restrict__ U2,
    const float* __restrict__ W3, const float* __restrict__ W4, const float* __restrict__ W5,
    const float* __restrict__ bqw, const float* __restrict__ bqs, const float* __restrict__ bqp)
{
    __shared__ float As[32][128];         // [k][m]
    __shared__ float Bs[32][128];         // [k][n]
    __shared__ const float* rowp[128];

    int tid = threadIdx.x;
    int m0 = blockIdx.x * 128, n0 = blockIdx.y * 128;
    int kbase = blockIdx.z * 256;
    int seg = (m0 < ROW_SRC) ? 0 : (m0 < ROW_WORD) ? 1 : (m0 < ROW_WQW) ? 2 :
              (m0 < ROW_WQS) ? 3 : (m0 < ROW_WQP) ? 4 : 5;
    const float* W = (seg == 0) ? U0 : (seg == 1) ? U1 : (seg == 2) ? U2 :
                     (seg == 3) ? W3 : (seg == 4) ? W4 : W5;

    // row-pointer table for the gathered A tile
    {
        int r = m0 + tid;
        const float* p;
        if (r < ROW_SRC) {
            int q = r < 64 ? r : 63; int b = q >> 4, j = q & 15;
            p = sentb + (size_t)(j * BD + b) * DD;
        } else if (r < ROW_WORD) {
            int q = r - ROW_SRC; if (q > 1599) q = 1599;
            int b = q / SRCN, i = q - b * SRCN;
            p = srcb + (size_t)(i * BD + b) * DD;
        } else if (r < ROW_WQW) {
            int q = r - ROW_WORD; int b = q / 640, rem = q - b * 640;
            int s = rem / WORDN, w = rem - s * WORDN;
            p = wordb + (size_t)((w * BD + b) * SENTN + s) * DD;
        } else {
            int q = (r - ROW_WQW) & 255; if (q > BT - 1) q = BT - 1;
            p = source + (size_t)q * DD;
        }
        rowp[tid] = p;
    }

    int tgm = tid & 7;            // M group (A cols (tid&7)*4 + 32i)
    int nb = (tid >> 3) * 8;      // N base (0..120)

    unsigned long long acc[8][8]; // [M-pair][n]
#pragma unroll
    for (int i = 0; i < 8; i++)
#pragma unroll
        for (int j = 0; j < 8; j++) acc[i][j] = 0ull;

    for (int kc = 0; kc < 8; kc++) {
        int k0 = kbase + kc * 32;
        __syncthreads();
        // stage A: 128 rows x 32 k -> As[k][m]  (1024 float4-granules)
#pragma unroll
        for (int s = 0; s < 8; s++) {
            int g = tid + s * 128;
            int m = g & 127, kg = g >> 7;     // kg 0..7
            float4 v = *(const float4*)(rowp[m] + k0 + kg * 4);
            As[kg * 4 + 0][m] = v.x;
            As[kg * 4 + 1][m] = v.y;
            As[kg * 4 + 2][m] = v.z;
            As[kg * 4 + 3][m] = v.w;
        }
        // stage B: 32 k x 128 n natural (coalesced)
#pragma unroll
        for (int s = 0; s < 8; s++) {
            int g = tid + s * 128;
            int k = g >> 5, n4 = (g & 31) * 4;
            *(float4*)&Bs[k][n4] = *(const float4*)&W[(size_t)(k0 + k) * DD + n0 + n4];
        }
        __syncthreads();

#pragma unroll 4
        for (int k = 0; k < 32; k++) {
            // A fragment: 4 conflict-free LDS.128 -> 8 M-pairs
            float4 a0 = *(const float4*)&As[k][tgm * 4];
            float4 a1 = *(const float4*)&As[k][tgm * 4 + 32];
            float4 a2v = *(const float4*)&As[k][tgm * 4 + 64];
            float4 a3 = *(const float4*)&As[k][tgm * 4 + 96];
            unsigned long long a2[8];
            PACK2(a2[0], a0.x, a0.y); PACK2(a2[1], a0.z, a0.w);
            PACK2(a2[2], a1.x, a1.y); PACK2(a2[3], a1.z, a1.w);
            PACK2(a2[4], a2v.x, a2v.y); PACK2(a2[5], a2v.z, a2v.w);
            PACK2(a2[6], a3.x, a3.y); PACK2(a2[7], a3.z, a3.w);
            // B fragment: broadcast, duplicated into pairs
            float4 b0 = *(const float4*)&Bs[k][nb];
            float4 b1 = *(const float4*)&Bs[k][nb + 4];
            unsigned long long bd[8];
            PACK2(bd[0], b0.x, b0.x); PACK2(bd[1], b0.y, b0.y);
            PACK2(bd[2], b0.z, b0.z); PACK2(bd[3], b0.w, b0.w);
            PACK2(bd[4], b1.x, b1.x); PACK2(bd[5], b1.y, b1.y);
            PACK2(bd[6], b1.z, b1.z); PACK2(bd[7], b1.w, b1.w);
#pragma unroll
            for (int mp = 0; mp < 8; mp++)
#pragma unroll
                for (int j = 0; j < 8; j++)
                    FFMA2(acc[mp][j], a2[mp], bd[j]);
        }
    }

    // epilogue: half 0 carries the bias for wq segments
    float* dst = (blockIdx.z == 0) ? g_act0 : g_act1;
    const float* bias = (blockIdx.z != 0) ? (const float*)0 :
                        (seg == 3) ? bqw : (seg == 4) ? bqs : (seg == 5) ? bqp : (const float*)0;
    float bb[8];
#pragma unroll
    for (int j = 0; j < 8; j++) bb[j] = bias ? bias[n0 + nb + j] : 0.0f;

#pragma unroll
    for (int mp = 0; mp < 8; mp++) {
        int i = mp >> 1, sub = mp & 1;
        int m = m0 + tgm * 4 + 32 * i + 2 * sub;
        float lo[8], hi[8];
#pragma unroll
        for (int j = 0; j < 8; j++) {
            uint32_t l, h;
            UNPACK2(l, h, acc[mp][j]);
            lo[j] = __uint_as_float(l) + bb[j];
            hi[j] = __uint_as_float(h) + bb[j];
        }
        size_t r0 = (size_t)m * DD + n0 + nb;
        *(float4*)&dst[r0]          = make_float4(lo[0], lo[1], lo[2], lo[3]);
        *(float4*)&dst[r0 + 4]      = make_float4(lo[4], lo[5], lo[6], lo[7]);
        *(float4*)&dst[r0 + DD]     = make_float4(hi[0], hi[1], hi[2], hi[3]);
        *(float4*)&dst[r0 + DD + 4] = make_float4(hi[4], hi[5], hi[6], hi[7]);
    }
}

// ============================================================
// combine K-halves: g_act = g_act0 + g_act1
// ============================================================
__global__ __launch_bounds__(256) void combine_kernel()
{
    size_t i = ((size_t)blockIdx.x * 256 + threadIdx.x) * 4;
    float4 a = *(const float4*)&g_act0[i];
    float4 b = *(const float4*)&g_act1[i];
    *(float4*)&g_act[i] = make_float4(a.x + b.x, a.y + b.y, a.z + b.z, a.w + b.w);
}

// ============================================================
// sentence-level scores: one warp per j, wq row staged in smem
// ============================================================
__global__ __launch_bounds__(512) void sent_kernel(const float* __restrict__ v_sent)
{
    __shared__ float wq_s[DD];
    __shared__ float vs[DD];
    int row = blockIdx.x;
    int b = row / TD;
    int tid = threadIdx.x, lane = tid & 31, w = tid >> 5;
    wq_s[tid] = g_act[(size_t)(ROW_WQS + row) * DD + tid];
    vs[tid] = v_sent[tid];
    __syncthreads();
    const float* uh = g_act + (size_t)(b * 16 + w) * DD;
    float acc = 0.f;
#pragma unroll
    for (int it = 0; it < 4; it++) {
        int d = it * 128 + lane * 4;
        float4 u = *(const float4*)&uh[d];
        acc += vs[d + 0] * tanh_fast(wq_s[d + 0] + u.x);
        acc += vs[d + 1] * tanh_fast(wq_s[d + 1] + u.y);
        acc += vs[d + 2] * tanh_fast(wq_s[d + 2] + u.z);
        acc += vs[d + 3] * tanh_fast(wq_s[d + 3] + u.w);
    }
#pragma unroll
    for (int o = 16; o; o >>= 1) acc += __shfl_xor_sync(0xffffffffu, acc, o);
    if (lane == 0) g_sent[row * SENTN + w] = acc;
}

// ============================================================
// main score kernel (raw partial scores, d split in halves)
// ============================================================
#define SC_CHUNK 64
#define SC_STRIDE 68
__global__ __launch_bounds__(256) void score_kernel(
    const float* __restrict__ v_pass, const float* __restrict__ v_word)
{
    __shared__ float wq_s[16 * SC_STRIDE];
    __shared__ float uh_s[80 * SC_STRIDE];
    __shared__ float v_s[SC_CHUNK];
    int tid = threadIdx.x;
    int jt = blockIdx.x, tt = blockIdx.y;
    int b = blockIdx.z & 3, half = blockIdx.z >> 2;
    int t0 = tt * 16;
    bool is_src = (jt < 5);
    const float* wqb = g_act + (size_t)((is_src ? ROW_WQP : ROW_WQW) + b * TD) * DD;
    int uh0 = is_src ? (ROW_SRC + b * SRCN + jt * 80) : (ROW_WORD + b * 640 + (jt - 5) * 80);
    const float* v = is_src ? v_pass : v_word;
    int d_base = half * 256;

    int tx = tid & 15, ty = tid >> 4;
    float acc[5] = {0.f, 0.f, 0.f, 0.f, 0.f};

    for (int c = 0; c < 4; c++) {
        int d0 = d_base + c * SC_CHUNK;
        __syncthreads();
        {
            int r = tid >> 4, col = (tid & 15) << 2;
            *(float4*)&wq_s[r * SC_STRIDE + col] =
                *(const float4*)&wqb[(size_t)(t0 + r) * DD + d0 + col];
        }
        for (int i = tid; i < 80 * 16; i += 256) {
            int r = i >> 4, col = (i & 15) << 2;
            *(float4*)&uh_s[r * SC_STRIDE + col] =
                *(const float4*)&g_act[(size_t)(uh0 + r) * DD + d0 + col];
        }
        if (tid < SC_CHUNK) v_s[tid] = v[d0 + tid];
        __syncthreads();
#pragma unroll 4
        for (int d4 = 0; d4 < 16; d4++) {
            float4 w4 = *(const float4*)&wq_s[ty * SC_STRIDE + (d4 << 2)];
            float4 v4 = *(const float4*)&v_s[d4 << 2];
#pragma unroll
            for (int u = 0; u < 5; u++) {
                float4 u4 = *(const float4*)&uh_s[(tx + 16 * u) * SC_STRIDE + (d4 << 2)];
                acc[u] += v4.x * tanh_fast(w4.x + u4.x);
                acc[u] += v4.y * tanh_fast(w4.y + u4.y);
                acc[u] += v4.z * tanh_fast(w4.z + u4.z);
                acc[u] += v4.w * tanh_fast(w4.w + u4.w);
            }
        }
    }

    int t = t0 + ty;
    if (t < TD) {
        float* arow = (half ? g_align1 : g_align0) + (size_t)(b * TD + t) * SJ;
        int jcol0 = is_src ? jt * 80 : SRCN + (jt - 5) * 80;
#pragma unroll
        for (int u = 0; u < 5; u++)
            arow[jcol0 + tx + 16 * u] = acc[u];
    }
}

// ============================================================
// softmax: combine halves, hier multiply, mask, softmax
// ============================================================
__global__ __launch_bounds__(256) void softmax_kernel(
    const int* __restrict__ src_len, const int* __restrict__ word_len)
{
    __shared__ float sval[SJ];
    __shared__ float red[256];
    __shared__ float sents[SENTN];
    int row = blockIdx.x, tid = threadIdx.x;
    int b = row / TD;
    if (tid < SENTN) sents[tid] = g_sent[row * SENTN + tid];
    __syncthreads();
    int sl = src_len[b];
    for (int j = tid; j < SJ; j += 256) {
        float rv = g_align0[(size_t)row * SJ + j] + g_align1[(size_t)row * SJ + j];
        float val;
        if (j < SRCN) {
            val = (j < sl) ? rv : -1e30f;
        } else {
            int jw = j - SRCN; int s = jw / WORDN, w = jw - s * WORDN;
            val = (w < word_len[b * SENTN + s]) ? rv * sents[s] : -1e30f;
        }
        sval[j] = val;
    }
    __syncthreads();
    float m = -3.4e38f;
    for (int j = tid; j < SJ; j += 256) m = fmaxf(m, sval[j]);
    red[tid] = m; __syncthreads();
    for (int o = 128; o; o >>= 1) { if (tid < o) red[tid] = fmaxf(red[tid], red[tid + o]); __syncthreads(); }
    m = red[0]; __syncthreads();
    float s = 0.f;
    for (int j = tid; j < SJ; j += 256) { float e = __expf(sval[j] - m); sval[j] = e; s += e; }
    red[tid] = s; __syncthreads();
    for (int o = 128; o; o >>= 1) { if (tid < o) red[tid] += red[tid + o]; __syncthreads(); }
    float inv = 1.0f / red[0];
    for (int j = tid; j < SJ; j += 256) g_p[(size_t)row * SJ + j] = sval[j] * inv;
}

// ============================================================
// context: c[b,t,d] = sum_j p[b,t,j] * mem[b,j,d]
// ============================================================
__global__ __launch_bounds__(256) void context_kernel(
    const float* __restrict__ srcb, const float* __restrict__ wordb, float* __restrict__ out)
{
    __shared__ float p_s[50 * 80];
    __shared__ float m_s[80 * 33];
    int tid = threadIdx.x;
    int b = blockIdx.y;
    int d0 = blockIdx.x * 32;
    int tx = tid & 31, ty = tid >> 5;
    float acc[7] = {};

    for (int j0 = 0; j0 < SJ; j0 += 80) {
        __syncthreads();
        for (int i = tid; i < 50 * 80; i += 256) {
            int r = i / 80, c = i - r * 80;
            p_s[i] = g_p[(size_t)(b * TD + r) * SJ + j0 + c];
        }
        for (int i = tid; i < 80 * 32; i += 256) {
            int r = i >> 5, c = i & 31;
            int j = j0 + r;
            const float* mp;
            if (j < SRCN) mp = srcb + (size_t)(j * BD + b) * DD;
            else { int jw = j - SRCN; int s = jw / WORDN, w = jw - s * WORDN;
                   mp = wordb + (size_t)((w * BD + b) * SENTN + s) * DD; }
            m_s[r * 33 + c] = mp[d0 + c];
        }
        __syncthreads();
        for (int j = 0; j < 80; j++) {
            float mv = m_s[j * 33 + tx];
#pragma unroll
            for (int q = 0; q < 7; q++) {
                int t = ty + (q << 3);
                if (t < TD) acc[q] += p_s[t * 80 + j] * mv;
            }
        }
    }
#pragma unroll
    for (int q = 0; q < 7; q++) {
        int t = ty + (q << 3);
        if (t < TD) out[(size_t)(b * TD + t) * DD + d0 + tx] = acc[q];
    }
}

// ============================================================
extern "C" void kernel_launch(void* const* d_in, const int* in_sizes, int n_in,
                              void* d_out, int out_size)
{
    const float* source    = (const float*)d_in[0];
    const float* src_bank  = (const float*)d_in[1];
    const int*   src_len   = (const int*)  d_in[2];
    const float* sent_bank = (const float*)d_in[3];
    const float* word_bank = (const float*)d_in[5];
    const int*   word_len  = (const int*)  d_in[6];
    const float* Wq_word = (const float*)d_in[7];
    const float* bq_word = (const float*)d_in[8];
    const float* Uc_word = (const float*)d_in[9];
    const float* v_word  = (const float*)d_in[10];
    const float* Wq_sent = (const float*)d_in[11];
    const float* bq_sent = (const float*)d_in[12];
    const float* Uc_sent = (const float*)d_in[13];
    const float* v_sent  = (const float*)d_in[14];
    const float* Wq_pass = (const float*)d_in[15];
    const float* bq_pass = (const float*)d_in[16];
    const float* Uc_pass = (const float*)d_in[17];
    const float* v_pass  = (const float*)d_in[18];
    float* out = (float*)d_out;

    ffma2_gemm<<<dim3(40, 4, 2), 128>>>(
        sent_bank, src_bank, word_bank, source,
        Uc_sent, Uc_pass, Uc_word, Wq_word, Wq_sent, Wq_pass,
        bq_word, bq_sent, bq_pass);
    combine_kernel<<<2560, 256>>>();
    sent_kernel<<<200, 512>>>(v_sent);
    score_kernel<<<dim3(13, 4, 8), 256>>>(v_pass, v_word);
    softmax_kernel<<<200, 256>>>(src_len, word_len);
    context_kernel<<<dim3(16, 4), 256>>>(src_bank, word_bank, out);
}

// round 9
// speedup vs baseline: 1.4298x; 1.1151x over previous
#include <cuda_runtime.h>
#include <cstdint>

#define BD 4
#define TD 50
#define DD 512
#define SRCN 400
#define SENTN 16
#define WORDN 40
#define SJ 1040
#define BT 200

// ---- unified GEMM row layout (segments padded to 128-row tiles) ----
#define MROWS 5120
#define ROW_SENT 0
#define ROW_SRC 128
#define ROW_WORD 1792
#define ROW_WQW 4352
#define ROW_WQS 4608
#define ROW_WQP 4864

// ---- scratch (device globals) ----
__device__ float g_act[MROWS * DD];            // all projections, fp32
__device__ float g_sent[BT * SENTN];
__device__ float g_align0[BT * SJ];
__device__ float g_align1[BT * SJ];
__device__ float g_p[BT * SJ];

__device__ __forceinline__ float tanh_fast(float x) {
    float y;
    asm("tanh.approx.f32 %0, %1;" : "=f"(y) : "f"(x));
    return y;
}

// tf32 helpers
__device__ __forceinline__ float tf32_rna(float x) {
    uint32_t h;
    asm("cvt.rna.tf32.f32 %0, %1;" : "=r"(h) : "f"(x));
    return __uint_as_float(h);
}

#define MMA_TF32(d, a, b) \
    asm volatile("mma.sync.aligned.m16n8k8.row.col.f32.tf32.tf32.f32 " \
        "{%0,%1,%2,%3}, {%4,%5,%6,%7}, {%8,%9}, {%0,%1,%2,%3};" \
        : "+f"((d)[0]), "+f"((d)[1]), "+f"((d)[2]), "+f"((d)[3]) \
        : "r"((a)[0]), "r"((a)[1]), "r"((a)[2]), "r"((a)[3]), "r"((b)[0]), "r"((b)[1]))

// ============================================================
// 3xTF32 mma GEMM: g_act[5120][512] = gather(A) @ W_seg (+bias)
// CTA tile 128(M) x 64(N), K=512, 128 threads (4 warps, warp tile 32x64).
// grid (40, 8). smem: Ahi[128][36] Alo[128][36] Bhi[32][72] Blo[32][72].
// A-frag banks (4*gr+gc)%32, B-frag banks (8*gc+gr)%32 -> conflict-free.
// ============================================================
#define AST 36
#define BST 72
#define SM_ROWP 0
#define SM_AHI (1024 / 4)                 // float index
#define SM_ALO (SM_AHI + 128 * AST)
#define SM_BHI (SM_ALO + 128 * AST)
#define SM_BLO (SM_BHI + 32 * BST)
#define SMEM_GEMM_BYTES (1024 + (2 * 128 * AST + 2 * 32 * BST) * 4)

__global__ __launch_bounds__(128, 4) void tf32_gemm(
    const float* __restrict__ sentb, const float* __restrict__ srcb,
    const float* __restrict__ wordb, const float* __restrict__ source,
    const float* __restrict__ U0, const float* __restrict__ U1, const float* __restrict__ U2,
    const float* __restrict__ W3, const float* __restrict__ W4, const float* __restrict__ W5,
    const float* __restrict__ bqw, const float* __restrict__ bqs, const float* __restrict__ bqp)
{
    extern __shared__ __align__(16) char smraw[];
    const float** rowp = (const float**)smraw;
    float* Ahi = (float*)smraw + SM_AHI;
    float* Alo = (float*)smraw + SM_ALO;
    float* Bhi = (float*)smraw + SM_BHI;
    float* Blo = (float*)smraw + SM_BLO;

    int tid = threadIdx.x, lane = tid & 31, wid = tid >> 5;
    int m0 = blockIdx.x * 128, n0 = blockIdx.y * 64;
    int seg = (m0 < ROW_SRC) ? 0 : (m0 < ROW_WORD) ? 1 : (m0 < ROW_WQW) ? 2 :
              (m0 < ROW_WQS) ? 3 : (m0 < ROW_WQP) ? 4 : 5;
    const float* W = (seg == 0) ? U0 : (seg == 1) ? U1 : (seg == 2) ? U2 :
                     (seg == 3) ? W3 : (seg == 4) ? W4 : W5;

    // gather row-pointer table
    {
        int r = m0 + tid;
        const float* p;
        if (r < ROW_SRC) {
            int q = r < 64 ? r : 63; int b = q >> 4, j = q & 15;
            p = sentb + (size_t)(j * BD + b) * DD;
        } else if (r < ROW_WORD) {
            int q = r - ROW_SRC; if (q > 1599) q = 1599;
            int b = q / SRCN, i = q - b * SRCN;
            p = srcb + (size_t)(i * BD + b) * DD;
        } else if (r < ROW_WQW) {
            int q = r - ROW_WORD; int b = q / 640, rem = q - b * 640;
            int s = rem / WORDN, w = rem - s * WORDN;
            p = wordb + (size_t)((w * BD + b) * SENTN + s) * DD;
        } else {
            int q = (r - ROW_WQW) & 255; if (q > BT - 1) q = BT - 1;
            p = source + (size_t)q * DD;
        }
        rowp[tid] = p;
    }

    int gr = lane >> 2, gc = lane & 3;
    float acc[2][8][4];
#pragma unroll
    for (int mt = 0; mt < 2; mt++)
#pragma unroll
        for (int nt = 0; nt < 8; nt++)
#pragma unroll
            for (int c = 0; c < 4; c++) acc[mt][nt][c] = 0.0f;

    int ak4 = (tid & 7) * 4;              // A stage k-offset within chunk
    for (int kc = 0; kc < 16; kc++) {
        int k0 = kc * 32;
        __syncthreads();
        // stage A: 128 rows x 32 k (8 lanes coalesced per row)
#pragma unroll
        for (int s = 0; s < 8; s++) {
            int row = (tid >> 3) + s * 16;
            float4 v = *(const float4*)(rowp[row] + k0 + ak4);
            float hx = tf32_rna(v.x), hy = tf32_rna(v.y), hz = tf32_rna(v.z), hw = tf32_rna(v.w);
            *(float4*)&Ahi[row * AST + ak4] = make_float4(hx, hy, hz, hw);
            *(float4*)&Alo[row * AST + ak4] = make_float4(v.x - hx, v.y - hy, v.z - hz, v.w - hw);
        }
        // stage B: 32 k x 64 n (coalesced along n)
#pragma unroll
        for (int s = 0; s < 4; s++) {
            int g = tid + s * 128;
            int k = g >> 4, c4 = (g & 15) * 4;
            float4 v = *(const float4*)&W[(size_t)(k0 + k) * DD + n0 + c4];
            float hx = tf32_rna(v.x), hy = tf32_rna(v.y), hz = tf32_rna(v.z), hw = tf32_rna(v.w);
            *(float4*)&Bhi[k * BST + c4] = make_float4(hx, hy, hz, hw);
            *(float4*)&Blo[k * BST + c4] = make_float4(v.x - hx, v.y - hy, v.z - hz, v.w - hw);
        }
        __syncthreads();

#pragma unroll
        for (int k8 = 0; k8 < 4; k8++) {
            int kk = k8 * 8;
            uint32_t ahf[2][4], alf[2][4];
#pragma unroll
            for (int mt = 0; mt < 2; mt++) {
                int mr = wid * 32 + mt * 16 + gr;
                ahf[mt][0] = __float_as_uint(Ahi[mr * AST + kk + gc]);
                ahf[mt][1] = __float_as_uint(Ahi[(mr + 8) * AST + kk + gc]);
                ahf[mt][2] = __float_as_uint(Ahi[mr * AST + kk + gc + 4]);
                ahf[mt][3] = __float_as_uint(Ahi[(mr + 8) * AST + kk + gc + 4]);
                alf[mt][0] = __float_as_uint(Alo[mr * AST + kk + gc]);
                alf[mt][1] = __float_as_uint(Alo[(mr + 8) * AST + kk + gc]);
                alf[mt][2] = __float_as_uint(Alo[mr * AST + kk + gc + 4]);
                alf[mt][3] = __float_as_uint(Alo[(mr + 8) * AST + kk + gc + 4]);
            }
#pragma unroll
            for (int nt = 0; nt < 8; nt++) {
                uint32_t bhf[2], blf[2];
                bhf[0] = __float_as_uint(Bhi[(kk + gc) * BST + nt * 8 + gr]);
                bhf[1] = __float_as_uint(Bhi[(kk + gc + 4) * BST + nt * 8 + gr]);
                blf[0] = __float_as_uint(Blo[(kk + gc) * BST + nt * 8 + gr]);
                blf[1] = __float_as_uint(Blo[(kk + gc + 4) * BST + nt * 8 + gr]);
#pragma unroll
                for (int mt = 0; mt < 2; mt++) {
                    MMA_TF32(acc[mt][nt], ahf[mt], bhf);
                    MMA_TF32(acc[mt][nt], ahf[mt], blf);
                    MMA_TF32(acc[mt][nt], alf[mt], bhf);
                }
            }
        }
    }

    // epilogue: fused bias on wq segments, direct store to g_act
    const float* bias = (seg == 3) ? bqw : (seg == 4) ? bqs : (seg == 5) ? bqp : (const float*)0;
#pragma unroll
    for (int nt = 0; nt < 8; nt++) {
        int n = n0 + nt * 8 + gc * 2;
        float b0 = bias ? bias[n] : 0.0f;
        float b1 = bias ? bias[n + 1] : 0.0f;
#pragma unroll
        for (int mt = 0; mt < 2; mt++) {
            int m = m0 + wid * 32 + mt * 16 + gr;
            *(float2*)&g_act[(size_t)m * DD + n] =
                make_float2(acc[mt][nt][0] + b0, acc[mt][nt][1] + b1);
            *(float2*)&g_act[(size_t)(m + 8) * DD + n] =
                make_float2(acc[mt][nt][2] + b0, acc[mt][nt][3] + b1);
        }
    }
}

// ============================================================
// sentence-level scores: one warp per j, wq row staged in smem
// ============================================================
__global__ __launch_bounds__(512) void sent_kernel(const float* __restrict__ v_sent)
{
    __shared__ float wq_s[DD];
    __shared__ float vs[DD];
    int row = blockIdx.x;
    int b = row / TD;
    int tid = threadIdx.x, lane = tid & 31, w = tid >> 5;
    wq_s[tid] = g_act[(size_t)(ROW_WQS + row) * DD + tid];
    vs[tid] = v_sent[tid];
    __syncthreads();
    const float* uh = g_act + (size_t)(b * 16 + w) * DD;
    float acc = 0.f;
#pragma unroll
    for (int it = 0; it < 4; it++) {
        int d = it * 128 + lane * 4;
        float4 u = *(const float4*)&uh[d];
        acc += vs[d + 0] * tanh_fast(wq_s[d + 0] + u.x);
        acc += vs[d + 1] * tanh_fast(wq_s[d + 1] + u.y);
        acc += vs[d + 2] * tanh_fast(wq_s[d + 2] + u.z);
        acc += vs[d + 3] * tanh_fast(wq_s[d + 3] + u.w);
    }
#pragma unroll
    for (int o = 16; o; o >>= 1) acc += __shfl_xor_sync(0xffffffffu, acc, o);
    if (lane == 0) g_sent[row * SENTN + w] = acc;
}

// ============================================================
// main score kernel (raw partial scores, d split in halves)
// ============================================================
#define SC_CHUNK 64
#define SC_STRIDE 68
__global__ __launch_bounds__(256) void score_kernel(
    const float* __restrict__ v_pass, const float* __restrict__ v_word)
{
    __shared__ float wq_s[16 * SC_STRIDE];
    __shared__ float uh_s[80 * SC_STRIDE];
    __shared__ float v_s[SC_CHUNK];
    int tid = threadIdx.x;
    int jt = blockIdx.x, tt = blockIdx.y;
    int b = blockIdx.z & 3, half = blockIdx.z >> 2;
    int t0 = tt * 16;
    bool is_src = (jt < 5);
    const float* wqb = g_act + (size_t)((is_src ? ROW_WQP : ROW_WQW) + b * TD) * DD;
    int uh0 = is_src ? (ROW_SRC + b * SRCN + jt * 80) : (ROW_WORD + b * 640 + (jt - 5) * 80);
    const float* v = is_src ? v_pass : v_word;
    int d_base = half * 256;

    int tx = tid & 15, ty = tid >> 4;
    float acc[5] = {0.f, 0.f, 0.f, 0.f, 0.f};

    for (int c = 0; c < 4; c++) {
        int d0 = d_base + c * SC_CHUNK;
        __syncthreads();
        {
            int r = tid >> 4, col = (tid & 15) << 2;
            *(float4*)&wq_s[r * SC_STRIDE + col] =
                *(const float4*)&wqb[(size_t)(t0 + r) * DD + d0 + col];
        }
        for (int i = tid; i < 80 * 16; i += 256) {
            int r = i >> 4, col = (i & 15) << 2;
            *(float4*)&uh_s[r * SC_STRIDE + col] =
                *(const float4*)&g_act[(size_t)(uh0 + r) * DD + d0 + col];
        }
        if (tid < SC_CHUNK) v_s[tid] = v[d0 + tid];
        __syncthreads();
#pragma unroll 4
        for (int d4 = 0; d4 < 16; d4++) {
            float4 w4 = *(const float4*)&wq_s[ty * SC_STRIDE + (d4 << 2)];
            float4 v4 = *(const float4*)&v_s[d4 << 2];
#pragma unroll
            for (int u = 0; u < 5; u++) {
                float4 u4 = *(const float4*)&uh_s[(tx + 16 * u) * SC_STRIDE + (d4 << 2)];
                acc[u] += v4.x * tanh_fast(w4.x + u4.x);
                acc[u] += v4.y * tanh_fast(w4.y + u4.y);
                acc[u] += v4.z * tanh_fast(w4.z + u4.z);
                acc[u] += v4.w * tanh_fast(w4.w + u4.w);
            }
        }
    }

    int t = t0 + ty;
    if (t < TD) {
        float* arow = (half ? g_align1 : g_align0) + (size_t)(b * TD + t) * SJ;
        int jcol0 = is_src ? jt * 80 : SRCN + (jt - 5) * 80;
#pragma unroll
        for (int u = 0; u < 5; u++)
            arow[jcol0 + tx + 16 * u] = acc[u];
    }
}

// ============================================================
// softmax: combine halves, hier multiply, mask, softmax
// ============================================================
__global__ __launch_bounds__(256) void softmax_kernel(
    const int* __restrict__ src_len, const int* __restrict__ word_len)
{
    __shared__ float sval[SJ];
    __shared__ float red[256];
    __shared__ float sents[SENTN];
    int row = blockIdx.x, tid = threadIdx.x;
    int b = row / TD;
    if (tid < SENTN) sents[tid] = g_sent[row * SENTN + tid];
    __syncthreads();
    int sl = src_len[b];
    for (int j = tid; j < SJ; j += 256) {
        float rv = g_align0[(size_t)row * SJ + j] + g_align1[(size_t)row * SJ + j];
        float val;
        if (j < SRCN) {
            val = (j < sl) ? rv : -1e30f;
        } else {
            int jw = j - SRCN; int s = jw / WORDN, w = jw - s * WORDN;
            val = (w < word_len[b * SENTN + s]) ? rv * sents[s] : -1e30f;
        }
        sval[j] = val;
    }
    __syncthreads();
    float m = -3.4e38f;
    for (int j = tid; j < SJ; j += 256) m = fmaxf(m, sval[j]);
    red[tid] = m; __syncthreads();
    for (int o = 128; o; o >>= 1) { if (tid < o) red[tid] = fmaxf(red[tid], red[tid + o]); __syncthreads(); }
    m = red[0]; __syncthreads();
    float s = 0.f;
    for (int j = tid; j < SJ; j += 256) { float e = __expf(sval[j] - m); sval[j] = e; s += e; }
    red[tid] = s; __syncthreads();
    for (int o = 128; o; o >>= 1) { if (tid < o) red[tid] += red[tid + o]; __syncthreads(); }
    float inv = 1.0f / red[0];
    for (int j = tid; j < SJ; j += 256) g_p[(size_t)row * SJ + j] = sval[j] * inv;
}

// ============================================================
// context: c[b,t,d] = sum_j p[b,t,j] * mem[b,j,d]
// ============================================================
__global__ __launch_bounds__(256) void context_kernel(
    const float* __restrict__ srcb, const float* __restrict__ wordb, float* __restrict__ out)
{
    __shared__ float p_s[50 * 80];
    __shared__ float m_s[80 * 33];
    int tid = threadIdx.x;
    int b = blockIdx.y;
    int d0 = blockIdx.x * 32;
    int tx = tid & 31, ty = tid >> 5;
    float acc[7] = {};

    for (int j0 = 0; j0 < SJ; j0 += 80) {
        __syncthreads();
        for (int i = tid; i < 50 * 80; i += 256) {
            int r = i / 80, c = i - r * 80;
            p_s[i] = g_p[(size_t)(b * TD + r) * SJ + j0 + c];
        }
        for (int i = tid; i < 80 * 32; i += 256) {
            int r = i >> 5, c = i & 31;
            int j = j0 + r;
            const float* mp;
            if (j < SRCN) mp = srcb + (size_t)(j * BD + b) * DD;
            else { int jw = j - SRCN; int s = jw / WORDN, w = jw - s * WORDN;
                   mp = wordb + (size_t)((w * BD + b) * SENTN + s) * DD; }
            m_s[r * 33 + c] = mp[d0 + c];
        }
        __syncthreads();
        for (int j = 0; j < 80; j++) {
            float mv = m_s[j * 33 + tx];
#pragma unroll
            for (int q = 0; q < 7; q++) {
                int t = ty + (q << 3);
                if (t < TD) acc[q] += p_s[t * 80 + j] * mv;
            }
        }
    }
#pragma unroll
    for (int q = 0; q < 7; q++) {
        int t = ty + (q << 3);
        if (t < TD) out[(size_t)(b * TD + t) * DD + d0 + tx] = acc[q];
    }
}

// ============================================================
extern "C" void kernel_launch(void* const* d_in, const int* in_sizes, int n_in,
                              void* d_out, int out_size)
{
    const float* source    = (const float*)d_in[0];
    const float* src_bank  = (const float*)d_in[1];
    const int*   src_len   = (const int*)  d_in[2];
    const float* sent_bank = (const float*)d_in[3];
    const float* word_bank = (const float*)d_in[5];
    const int*   word_len  = (const int*)  d_in[6];
    const float* Wq_word = (const float*)d_in[7];
    const float* bq_word = (const float*)d_in[8];
    const float* Uc_word = (const float*)d_in[9];
    const float* v_word  = (const float*)d_in[10];
    const float* Wq_sent = (const float*)d_in[11];
    const float* bq_sent = (const float*)d_in[12];
    const float* Uc_sent = (const float*)d_in[13];
    const float* v_sent  = (const float*)d_in[14];
    const float* Wq_pass = (const float*)d_in[15];
    const float* bq_pass = (const float*)d_in[16];
    const float* Uc_pass = (const float*)d_in[17];
    const float* v_pass  = (const float*)d_in[18];
    float* out = (float*)d_out;

    cudaFuncSetAttribute(tf32_gemm, cudaFuncAttributeMaxDynamicSharedMemorySize, SMEM_GEMM_BYTES);

    tf32_gemm<<<dim3(40, 8), 128, SMEM_GEMM_BYTES>>>(
        sent_bank, src_bank, word_bank, source,
        Uc_sent, Uc_pass, Uc_word, Wq_word, Wq_sent, Wq_pass,
        bq_word, bq_sent, bq_pass);
    sent_kernel<<<200, 512>>>(v_sent);
    score_kernel<<<dim3(13, 4, 8), 256>>>(v_pass, v_word);
    softmax_kernel<<<200, 256>>>(src_len, word_len);
    context_kernel<<<dim3(16, 4), 256>>>(src_bank, word_bank, out);
}

// round 12
// speedup vs baseline: 1.5916x; 1.1132x over previous
#include <cuda_runtime.h>
#include <cuda_bf16.h>
#include <cstdint>

#define BD 4
#define TD 50
#define DD 512
#define SRCN 400
#define SENTN 16
#define WORDN 40
#define SJ 1040
#define BT 200

// ---- unified GEMM row layout (segments padded to 128-row tiles) ----
#define MROWS 5120
#define ROW_SENT 0
#define ROW_SRC 128
#define ROW_WORD 1792
#define ROW_WQW 4352
#define ROW_WQS 4608
#define ROW_WQP 4864

// ---- scratch (device globals) ----
__device__ float g_act[MROWS * DD];            // all projections, fp32
__device__ float g_sent[BT * SENTN];
__device__ float g_align0[BT * SJ];
__device__ float g_align1[BT * SJ];
__device__ float g_p[BT * SJ];

__device__ __forceinline__ float tanh_fast(float x) {
    float y;
    asm("tanh.approx.f32 %0, %1;" : "=f"(y) : "f"(x));
    return y;
}

__device__ __forceinline__ uint32_t smem_u32(const void* p) {
    uint32_t a;
    asm("{ .reg .u64 t; cvta.to.shared.u64 t, %1; cvt.u32.u64 %0, t; }" : "=r"(a) : "l"(p));
    return a;
}

#define MMA_BF16(d, a, b) \
    asm volatile("mma.sync.aligned.m16n8k16.row.col.f32.bf16.bf16.f32 " \
        "{%0,%1,%2,%3}, {%4,%5,%6,%7}, {%8,%9}, {%0,%1,%2,%3};" \
        : "+f"((d)[0]), "+f"((d)[1]), "+f"((d)[2]), "+f"((d)[3]) \
        : "r"((a)[0]), "r"((a)[1]), "r"((a)[2]), "r"((a)[3]), "r"((b)[0]), "r"((b)[1]))

#define LDSM_X4_T(r, addr) \
    asm volatile("ldmatrix.sync.aligned.m8n8.x4.trans.shared.b16 {%0,%1,%2,%3}, [%4];" \
        : "=r"((r)[0]), "=r"((r)[1]), "=r"((r)[2]), "=r"((r)[3]) : "r"(addr))

__device__ __forceinline__ uint32_t pack_bf2(float a, float b) {
    __nv_bfloat162 t = __floats2bfloat162_rn(a, b);
    return *(uint32_t*)&t;
}

// ============================================================
// split-bf16 (3-pass) mma GEMM: g_act[5120][512] = gather(A) @ W_seg (+bias)
// CTA tile 128(M) x 64(N), K=512, 128 threads (4 warps, warp tile 32x64).
// grid (40, 8). smem ~30.7 KB static.
// A pairs: [128][20] u32, banks (4m+idx)%32 conflict-free.
// B: [32][72] half rows (144B stride) -> LDSM.x4.trans conflict-free.
// ============================================================
#define APST 20     // A pair-row stride (u32)
#define BSTH 72     // B row stride (halves)

__global__ __launch_bounds__(128, 4) void bf16_gemm(
    const float* __restrict__ sentb, const float* __restrict__ srcb,
    const float* __restrict__ wordb, const float* __restrict__ source,
    const float* __restrict__ U0, const float* __restrict__ U1, const float* __restrict__ U2,
    const float* __restrict__ W3, const float* __restrict__ W4, const float* __restrict__ W5,
    const float* __restrict__ bqw, const float* __restrict__ bqs, const float* __restrict__ bqp)
{
    __shared__ const float* rowp[128];
    __shared__ uint32_t Ahi[128 * APST];
    __shared__ uint32_t Alo[128 * APST];
    __shared__ __nv_bfloat16 Bh[32 * BSTH];
    __shared__ __nv_bfloat16 Bl[32 * BSTH];

    int tid = threadIdx.x, lane = tid & 31, wid = tid >> 5;
    int m0 = blockIdx.x * 128, n0 = blockIdx.y * 64;
    int seg = (m0 < ROW_SRC) ? 0 : (m0 < ROW_WORD) ? 1 : (m0 < ROW_WQW) ? 2 :
              (m0 < ROW_WQS) ? 3 : (m0 < ROW_WQP) ? 4 : 5;
    const float* W = (seg == 0) ? U0 : (seg == 1) ? U1 : (seg == 2) ? U2 :
                     (seg == 3) ? W3 : (seg == 4) ? W4 : W5;

    // gather row-pointer table
    {
        int r = m0 + tid;
        const float* p;
        if (r < ROW_SRC) {
            int q = r < 64 ? r : 63; int b = q >> 4, j = q & 15;
            p = sentb + (size_t)(j * BD + b) * DD;
        } else if (r < ROW_WORD) {
            int q = r - ROW_SRC; if (q > 1599) q = 1599;
            int b = q / SRCN, i = q - b * SRCN;
            p = srcb + (size_t)(i * BD + b) * DD;
        } else if (r < ROW_WQW) {
            int q = r - ROW_WORD; int b = q / 640, rem = q - b * 640;
            int s = rem / WORDN, w = rem - s * WORDN;
            p = wordb + (size_t)((w * BD + b) * SENTN + s) * DD;
        } else {
            int q = (r - ROW_WQW) & 255; if (q > BT - 1) q = BT - 1;
            p = source + (size_t)q * DD;
        }
        rowp[tid] = p;
    }

    uint32_t bh_base = smem_u32(Bh);
    uint32_t bl_base = smem_u32(Bl);
    int gr = lane >> 2, gc = lane & 3;

    float acc[2][8][4];
#pragma unroll
    for (int mt = 0; mt < 2; mt++)
#pragma unroll
        for (int nt = 0; nt < 8; nt++)
#pragma unroll
            for (int c = 0; c < 4; c++) acc[mt][nt][c] = 0.0f;

    // LDSM lane address offset (halves): quad = lane>>3, lrow = lane&7
    int quad = lane >> 3, lrow = lane & 7;
    int ldsm_off = ((quad & 1) * 8 + lrow) * BSTH + (quad >> 1) * 8;

    for (int kc = 0; kc < 16; kc++) {
        int k0 = kc * 32;
        __syncthreads();
        // stage A: 128 rows x 32 k as bf16 hi/lo pairs
#pragma unroll
        for (int s = 0; s < 8; s++) {
            int row = (tid >> 3) + s * 16;
            float4 v = *(const float4*)(rowp[row] + k0 + (tid & 7) * 4);
            __nv_bfloat162 h01 = __floats2bfloat162_rn(v.x, v.y);
            __nv_bfloat162 h23 = __floats2bfloat162_rn(v.z, v.w);
            float l0 = v.x - __low2float(h01), l1 = v.y - __high2float(h01);
            float l2 = v.z - __low2float(h23), l3 = v.w - __high2float(h23);
            int o = row * APST + (tid & 7) * 2;
            Ahi[o]     = *(uint32_t*)&h01;
            Ahi[o + 1] = *(uint32_t*)&h23;
            Alo[o]     = pack_bf2(l0, l1);
            Alo[o + 1] = pack_bf2(l2, l3);
        }
        // stage B: 32 k x 64 n, natural [k][n]
#pragma unroll
        for (int s = 0; s < 4; s++) {
            int g = tid + s * 128;
            int k = g >> 4, n4 = (g & 15) * 4;
            float4 v = *(const float4*)&W[(size_t)(k0 + k) * DD + n0 + n4];
            __nv_bfloat162 h01 = __floats2bfloat162_rn(v.x, v.y);
            __nv_bfloat162 h23 = __floats2bfloat162_rn(v.z, v.w);
            float l0 = v.x - __low2float(h01), l1 = v.y - __high2float(h01);
            float l2 = v.z - __low2float(h23), l3 = v.w - __high2float(h23);
            *(uint2*)&Bh[k * BSTH + n4] = make_uint2(*(uint32_t*)&h01, *(uint32_t*)&h23);
            *(uint2*)&Bl[k * BSTH + n4] = make_uint2(pack_bf2(l0, l1), pack_bf2(l2, l3));
        }
        __syncthreads();

#pragma unroll
        for (int step = 0; step < 2; step++) {
            int kkp = step * 8;       // A pair offset
            int kk2 = step * 16;      // B k-row offset
            uint32_t ah[2][4], al[2][4];
#pragma unroll
            for (int mt = 0; mt < 2; mt++) {
                int mr = wid * 32 + mt * 16 + gr;
                ah[mt][0] = Ahi[mr * APST + kkp + gc];
                ah[mt][1] = Ahi[(mr + 8) * APST + kkp + gc];
                ah[mt][2] = Ahi[mr * APST + kkp + gc + 4];
                ah[mt][3] = Ahi[(mr + 8) * APST + kkp + gc + 4];
                al[mt][0] = Alo[mr * APST + kkp + gc];
                al[mt][1] = Alo[(mr + 8) * APST + kkp + gc];
                al[mt][2] = Alo[mr * APST + kkp + gc + 4];
                al[mt][3] = Alo[(mr + 8) * APST + kkp + gc + 4];
            }
#pragma unroll
            for (int np = 0; np < 4; np++) {
                uint32_t off = (uint32_t)((kk2 * BSTH + np * 16 + ldsm_off) * 2);
                uint32_t bh4[4], bl4[4];
                LDSM_X4_T(bh4, bh_base + off);
                LDSM_X4_T(bl4, bl_base + off);
#pragma unroll
                for (int sub = 0; sub < 2; sub++) {
#pragma unroll
                    for (int mt = 0; mt < 2; mt++) {
                        MMA_BF16(acc[mt][np * 2 + sub], ah[mt], &bh4[sub * 2]);
                        MMA_BF16(acc[mt][np * 2 + sub], ah[mt], &bl4[sub * 2]);
                        MMA_BF16(acc[mt][np * 2 + sub], al[mt], &bh4[sub * 2]);
                    }
                }
            }
        }
    }

    // epilogue: fused bias on wq segments, direct store
    const float* bias = (seg == 3) ? bqw : (seg == 4) ? bqs : (seg == 5) ? bqp : (const float*)0;
#pragma unroll
    for (int nt = 0; nt < 8; nt++) {
        int n = n0 + nt * 8 + gc * 2;
        float b0 = bias ? bias[n] : 0.0f;
        float b1 = bias ? bias[n + 1] : 0.0f;
#pragma unroll
        for (int mt = 0; mt < 2; mt++) {
            int m = m0 + wid * 32 + mt * 16 + gr;
            *(float2*)&g_act[(size_t)m * DD + n] =
                make_float2(acc[mt][nt][0] + b0, acc[mt][nt][1] + b1);
            *(float2*)&g_act[(size_t)(m + 8) * DD + n] =
                make_float2(acc[mt][nt][2] + b0, acc[mt][nt][3] + b1);
        }
    }
}

// ============================================================
// sentence-level scores: one warp per j, wq row staged in smem
// ============================================================
__global__ __launch_bounds__(512) void sent_kernel(const float* __restrict__ v_sent)
{
    __shared__ float wq_s[DD];
    __shared__ float vs[DD];
    int row = blockIdx.x;
    int b = row / TD;
    int tid = threadIdx.x, lane = tid & 31, w = tid >> 5;
    wq_s[tid] = g_act[(size_t)(ROW_WQS + row) * DD + tid];
    vs[tid] = v_sent[tid];
    __syncthreads();
    const float* uh = g_act + (size_t)(b * 16 + w) * DD;
    float acc = 0.f;
#pragma unroll
    for (int it = 0; it < 4; it++) {
        int d = it * 128 + lane * 4;
        float4 u = *(const float4*)&uh[d];
        acc += vs[d + 0] * tanh_fast(wq_s[d + 0] + u.x);
        acc += vs[d + 1] * tanh_fast(wq_s[d + 1] + u.y);
        acc += vs[d + 2] * tanh_fast(wq_s[d + 2] + u.z);
        acc += vs[d + 3] * tanh_fast(wq_s[d + 3] + u.w);
    }
#pragma unroll
    for (int o = 16; o; o >>= 1) acc += __shfl_xor_sync(0xffffffffu, acc, o);
    if (lane == 0) g_sent[row * SENTN + w] = acc;
}

// ============================================================
// main score kernel (raw partial scores, d split in halves)
// ============================================================
#define SC_CHUNK 64
#define SC_STRIDE 68
__global__ __launch_bounds__(256) void score_kernel(
    const float* __restrict__ v_pass, const float* __restrict__ v_word)
{
    __shared__ float wq_s[16 * SC_STRIDE];
    __shared__ float uh_s[80 * SC_STRIDE];
    __shared__ float v_s[SC_CHUNK];
    int tid = threadIdx.x;
    int jt = blockIdx.x, tt = blockIdx.y;
    int b = blockIdx.z & 3, half = blockIdx.z >> 2;
    int t0 = tt * 16;
    bool is_src = (jt < 5);
    const float* wqb = g_act + (size_t)((is_src ? ROW_WQP : ROW_WQW) + b * TD) * DD;
    int uh0 = is_src ? (ROW_SRC + b * SRCN + jt * 80) : (ROW_WORD + b * 640 + (jt - 5) * 80);
    const float* v = is_src ? v_pass : v_word;
    int d_base = half * 256;

    int tx = tid & 15, ty = tid >> 4;
    float acc[5] = {0.f, 0.f, 0.f, 0.f, 0.f};

    for (int c = 0; c < 4; c++) {
        int d0 = d_base + c * SC_CHUNK;
        __syncthreads();
        {
            int r = tid >> 4, col = (tid & 15) << 2;
            *(float4*)&wq_s[r * SC_STRIDE + col] =
                *(const float4*)&wqb[(size_t)(t0 + r) * DD + d0 + col];
        }
        for (int i = tid; i < 80 * 16; i += 256) {
            int r = i >> 4, col = (i & 15) << 2;
            *(float4*)&uh_s[r * SC_STRIDE + col] =
                *(const float4*)&g_act[(size_t)(uh0 + r) * DD + d0 + col];
        }
        if (tid < SC_CHUNK) v_s[tid] = v[d0 + tid];
        __syncthreads();
#pragma unroll 4
        for (int d4 = 0; d4 < 16; d4++) {
            float4 w4 = *(const float4*)&wq_s[ty * SC_STRIDE + (d4 << 2)];
            float4 v4 = *(const float4*)&v_s[d4 << 2];
#pragma unroll
            for (int u = 0; u < 5; u++) {
                float4 u4 = *(const float4*)&uh_s[(tx + 16 * u) * SC_STRIDE + (d4 << 2)];
                acc[u] += v4.x * tanh_fast(w4.x + u4.x);
                acc[u] += v4.y * tanh_fast(w4.y + u4.y);
                acc[u] += v4.z * tanh_fast(w4.z + u4.z);
                acc[u] += v4.w * tanh_fast(w4.w + u4.w);
            }
        }
    }

    int t = t0 + ty;
    if (t < TD) {
        float* arow = (half ? g_align1 : g_align0) + (size_t)(b * TD + t) * SJ;
        int jcol0 = is_src ? jt * 80 : SRCN + (jt - 5) * 80;
#pragma unroll
        for (int u = 0; u < 5; u++)
            arow[jcol0 + tx + 16 * u] = acc[u];
    }
}

// ============================================================
// softmax: combine halves, hier multiply, mask, softmax
// ============================================================
__global__ __launch_bounds__(256) void softmax_kernel(
    const int* __restrict__ src_len, const int* __restrict__ word_len)
{
    __shared__ float sval[SJ];
    __shared__ float red[256];
    __shared__ float sents[SENTN];
    int row = blockIdx.x, tid = threadIdx.x;
    int b = row / TD;
    if (tid < SENTN) sents[tid] = g_sent[row * SENTN + tid];
    __syncthreads();
    int sl = src_len[b];
    for (int j = tid; j < SJ; j += 256) {
        float rv = g_align0[(size_t)row * SJ + j] + g_align1[(size_t)row * SJ + j];
        float val;
        if (j < SRCN) {
            val = (j < sl) ? rv : -1e30f;
        } else {
            int jw = j - SRCN; int s = jw / WORDN, w = jw - s * WORDN;
            val = (w < word_len[b * SENTN + s]) ? rv * sents[s] : -1e30f;
        }
        sval[j] = val;
    }
    __syncthreads();
    float m = -3.4e38f;
    for (int j = tid; j < SJ; j += 256) m = fmaxf(m, sval[j]);
    red[tid] = m; __syncthreads();
    for (int o = 128; o; o >>= 1) { if (tid < o) red[tid] = fmaxf(red[tid], red[tid + o]); __syncthreads(); }
    m = red[0]; __syncthreads();
    float s = 0.f;
    for (int j = tid; j < SJ; j += 256) { float e = __expf(sval[j] - m); sval[j] = e; s += e; }
    red[tid] = s; __syncthreads();
    for (int o = 128; o; o >>= 1) { if (tid < o) red[tid] += red[tid + o]; __syncthreads(); }
    float inv = 1.0f / red[0];
    for (int j = tid; j < SJ; j += 256) g_p[(size_t)row * SJ + j] = sval[j] * inv;
}

// ============================================================
// context: c[b,t,d] = sum_j p[b,t,j] * mem[b,j,d]
// ============================================================
__global__ __launch_bounds__(256) void context_kernel(
    const float* __restrict__ srcb, const float* __restrict__ wordb, float* __restrict__ out)
{
    __shared__ float p_s[50 * 80];
    __shared__ float m_s[80 * 33];
    int tid = threadIdx.x;
    int b = blockIdx.y;
    int d0 = blockIdx.x * 32;
    int tx = tid & 31, ty = tid >> 5;
    float acc[7] = {};

    for (int j0 = 0; j0 < SJ; j0 += 80) {
        __syncthreads();
        for (int i = tid; i < 50 * 80; i += 256) {
            int r = i / 80, c = i - r * 80;
            p_s[i] = g_p[(size_t)(b * TD + r) * SJ + j0 + c];
        }
        for (int i = tid; i < 80 * 32; i += 256) {
            int r = i >> 5, c = i & 31;
            int j = j0 + r;
            const float* mp;
            if (j < SRCN) mp = srcb + (size_t)(j * BD + b) * DD;
            else { int jw = j - SRCN; int s = jw / WORDN, w = jw - s * WORDN;
                   mp = wordb + (size_t)((w * BD + b) * SENTN + s) * DD; }
            m_s[r * 33 + c] = mp[d0 + c];
        }
        __syncthreads();
        for (int j = 0; j < 80; j++) {
            float mv = m_s[j * 33 + tx];
#pragma unroll
            for (int q = 0; q < 7; q++) {
                int t = ty + (q << 3);
                if (t < TD) acc[q] += p_s[t * 80 + j] * mv;
            }
        }
    }
#pragma unroll
    for (int q = 0; q < 7; q++) {
        int t = ty + (q << 3);
        if (t < TD) out[(size_t)(b * TD + t) * DD + d0 + tx] = acc[q];
    }
}

// ============================================================
extern "C" void kernel_launch(void* const* d_in, const int* in_sizes, int n_in,
                              void* d_out, int out_size)
{
    const float* source    = (const float*)d_in[0];
    const float* src_bank  = (const float*)d_in[1];
    const int*   src_len   = (const int*)  d_in[2];
    const float* sent_bank = (const float*)d_in[3];
    const float* word_bank = (const float*)d_in[5];
    const int*   word_len  = (const int*)  d_in[6];
    const float* Wq_word = (const float*)d_in[7];
    const float* bq_word = (const float*)d_in[8];
    const float* Uc_word = (const float*)d_in[9];
    const float* v_word  = (const float*)d_in[10];
    const float* Wq_sent = (const float*)d_in[11];
    const float* bq_sent = (const float*)d_in[12];
    const float* Uc_sent = (const float*)d_in[13];
    const float* v_sent  = (const float*)d_in[14];
    const float* Wq_pass = (const float*)d_in[15];
    const float* bq_pass = (const float*)d_in[16];
    const float* Uc_pass = (const float*)d_in[17];
    const float* v_pass  = (const float*)d_in[18];
    float* out = (float*)d_out;

    bf16_gemm<<<dim3(40, 8), 128>>>(
        sent_bank, src_bank, word_bank, source,
        Uc_sent, Uc_pass, Uc_word, Wq_word, Wq_sent, Wq_pass,
        bq_word, bq_sent, bq_pass);
    sent_kernel<<<200, 512>>>(v_sent);
    score_kernel<<<dim3(13, 4, 8), 256>>>(v_pass, v_word);
    softmax_kernel<<<200, 256>>>(src_len, word_len);
    context_kernel<<<dim3(16, 4), 256>>>(src_bank, word_bank, out);
}

// round 13
// speedup vs baseline: 1.7006x; 1.0685x over previous
#include <cuda_runtime.h>
#include <cuda_bf16.h>
#include <cstdint>

#define BD 4
#define TD 50
#define DD 512
#define SRCN 400
#define SENTN 16
#define WORDN 40
#define SJ 1040
#define BT 200

#define MROWS 5120
#define ROW_SENT 0
#define ROW_SRC 128
#define ROW_WORD 1792
#define ROW_WQW 4352
#define ROW_WQS 4608
#define ROW_WQP 4864

// ---- scratch (device globals) ----
__device__ __nv_bfloat16 g_AhiG[MROWS * DD];
__device__ __nv_bfloat16 g_AloG[MROWS * DD];
__device__ __nv_bfloat16 g_BhG[6 * DD * DD];   // [set][k][n]
__device__ __nv_bfloat16 g_BlG[6 * DD * DD];
__device__ float g_act[MROWS * DD];
__device__ float g_sent[BT * SENTN];
__device__ float g_alignQ[4 * BT * SJ];        // d-quarter partial scores
__device__ float g_p[BT * SJ];

__device__ __forceinline__ float tanh_fast(float x) {
    float y;
    asm("tanh.approx.f32 %0, %1;" : "=f"(y) : "f"(x));
    return y;
}
__device__ __forceinline__ uint32_t smem_u32(const void* p) {
    uint32_t a;
    asm("{ .reg .u64 t; cvta.to.shared.u64 t, %1; cvt.u32.u64 %0, t; }" : "=r"(a) : "l"(p));
    return a;
}
#define MMA_BF16(d, a, b) \
    asm volatile("mma.sync.aligned.m16n8k16.row.col.f32.bf16.bf16.f32 " \
        "{%0,%1,%2,%3}, {%4,%5,%6,%7}, {%8,%9}, {%0,%1,%2,%3};" \
        : "+f"((d)[0]), "+f"((d)[1]), "+f"((d)[2]), "+f"((d)[3]) \
        : "r"((a)[0]), "r"((a)[1]), "r"((a)[2]), "r"((a)[3]), "r"((b)[0]), "r"((b)[1]))
#define LDSM_X4_T(r, addr) \
    asm volatile("ldmatrix.sync.aligned.m8n8.x4.trans.shared.b16 {%0,%1,%2,%3}, [%4];" \
        : "=r"((r)[0]), "=r"((r)[1]), "=r"((r)[2]), "=r"((r)[3]) : "r"(addr))
#define CP_ASYNC16(saddr, gptr) \
    asm volatile("cp.async.cg.shared.global [%0], [%1], 16;" :: "r"(saddr), "l"(gptr))
#define CP_COMMIT() asm volatile("cp.async.commit_group;" ::: "memory")
#define CP_WAIT1()  asm volatile("cp.async.wait_group 1;" ::: "memory")
#define CP_WAIT0()  asm volatile("cp.async.wait_group 0;" ::: "memory")

__device__ __forceinline__ uint32_t pack_bf2(float a, float b) {
    __nv_bfloat162 t = __floats2bfloat162_rn(a, b);
    return *(uint32_t*)&t;
}

// ============================================================
// conv_a: gather unified-A row, split fp32 -> bf16 hi/lo in gmem
// ============================================================
__global__ __launch_bounds__(128) void conv_a(
    const float* __restrict__ sentb, const float* __restrict__ srcb,
    const float* __restrict__ wordb, const float* __restrict__ source)
{
    int r = blockIdx.x;
    const float* p;
    if (r < ROW_SRC) {
        int q = r < 64 ? r : 63; int b = q >> 4, j = q & 15;
        p = sentb + (size_t)(j * BD + b) * DD;
    } else if (r < ROW_WORD) {
        int q = r - ROW_SRC; if (q > 1599) q = 1599;
        int b = q / SRCN, i = q - b * SRCN;
        p = srcb + (size_t)(i * BD + b) * DD;
    } else if (r < ROW_WQW) {
        int q = r - ROW_WORD; int b = q / 640, rem = q - b * 640;
        int s = rem / WORDN, w = rem - s * WORDN;
        p = wordb + (size_t)((w * BD + b) * SENTN + s) * DD;
    } else {
        int q = (r - ROW_WQW) & 255; if (q > BT - 1) q = BT - 1;
        p = source + (size_t)q * DD;
    }
    int d = threadIdx.x * 4;
    float4 x = *(const float4*)(p + d);
    __nv_bfloat162 h01 = __floats2bfloat162_rn(x.x, x.y);
    __nv_bfloat162 h23 = __floats2bfloat162_rn(x.z, x.w);
    float l0 = x.x - __low2float(h01), l1 = x.y - __high2float(h01);
    float l2 = x.z - __low2float(h23), l3 = x.w - __high2float(h23);
    size_t o = (size_t)r * DD + d;
    *(uint2*)&g_AhiG[o] = make_uint2(*(uint32_t*)&h01, *(uint32_t*)&h23);
    *(uint2*)&g_AloG[o] = make_uint2(pack_bf2(l0, l1), pack_bf2(l2, l3));
}

// ============================================================
// conv_b: split 6 weight matrices [k][n] fp32 -> bf16 hi/lo
// ============================================================
__global__ __launch_bounds__(128) void conv_b(
    const float* __restrict__ W0, const float* __restrict__ W1, const float* __restrict__ W2,
    const float* __restrict__ W3, const float* __restrict__ W4, const float* __restrict__ W5)
{
    int set = blockIdx.x >> 9, k = blockIdx.x & 511;
    const float* W = (set == 0) ? W0 : (set == 1) ? W1 : (set == 2) ? W2 :
                     (set == 3) ? W3 : (set == 4) ? W4 : W5;
    int n = threadIdx.x * 4;
    float4 x = *(const float4*)&W[(size_t)k * DD + n];
    __nv_bfloat162 h01 = __floats2bfloat162_rn(x.x, x.y);
    __nv_bfloat162 h23 = __floats2bfloat162_rn(x.z, x.w);
    float l0 = x.x - __low2float(h01), l1 = x.y - __high2float(h01);
    float l2 = x.z - __low2float(h23), l3 = x.w - __high2float(h23);
    size_t o = (size_t)set * DD * DD + (size_t)k * DD + n;
    *(uint2*)&g_BhG[o] = make_uint2(*(uint32_t*)&h01, *(uint32_t*)&h23);
    *(uint2*)&g_BlG[o] = make_uint2(pack_bf2(l0, l1), pack_bf2(l2, l3));
}

// ============================================================
// split-bf16 (3-pass) mma GEMM with cp.async 2-stage pipeline
// CTA 128(M) x 64(N), K=512, 128 threads, grid (40, 8).
// dynamic smem: Ahi[2][128*20]u32 | Alo[2] | Bh[2][32*36]u32 | Bl[2]
// ============================================================
#define APST 20
#define BST_U 36
#define BSTH 72
#define A_ST_SZ (128 * APST)
#define B_ST_SZ (32 * BST_U)
#define OFF_AHI(s) ((s) * A_ST_SZ)
#define OFF_ALO(s) (2 * A_ST_SZ + (s) * A_ST_SZ)
#define OFF_BH(s)  (4 * A_ST_SZ + (s) * B_ST_SZ)
#define OFF_BL(s)  (4 * A_ST_SZ + 2 * B_ST_SZ + (s) * B_ST_SZ)
#define SMEM_U     (4 * A_ST_SZ + 4 * B_ST_SZ)
#define SMEM_BYTES (SMEM_U * 4)

__device__ __forceinline__ void stage_chunk(
    uint32_t sb, int st, int kc, int m0, int n0, const __nv_bfloat16* BhSeg,
    const __nv_bfloat16* BlSeg, int tid)
{
    int k0 = kc * 32;
#pragma unroll
    for (int s = 0; s < 4; s++) {
        int g = tid + s * 128;
        int row = g >> 2, c8 = (g & 3) * 8;
        size_t go = (size_t)(m0 + row) * DD + k0 + c8;
        uint32_t so = 4 * (row * APST + (g & 3) * 4);
        CP_ASYNC16(sb + 4 * OFF_AHI(st) + so, g_AhiG + go);
        CP_ASYNC16(sb + 4 * OFF_ALO(st) + so, g_AloG + go);
    }
#pragma unroll
    for (int s = 0; s < 2; s++) {
        int g = tid + s * 128;
        int k = g >> 3, c8 = (g & 7) * 8;
        size_t go = (size_t)(k0 + k) * DD + n0 + c8;
        uint32_t so = 4 * (k * BST_U + (g & 7) * 4);
        CP_ASYNC16(sb + 4 * OFF_BH(st) + so, BhSeg + go);
        CP_ASYNC16(sb + 4 * OFF_BL(st) + so, BlSeg + go);
    }
}

__global__ __launch_bounds__(128, 3) void bf16_gemm(
    const float* __restrict__ bqw, const float* __restrict__ bqs, const float* __restrict__ bqp)
{
    extern __shared__ __align__(16) uint32_t smU[];
    uint32_t sb = smem_u32(smU);

    int tid = threadIdx.x, lane = tid & 31, wid = tid >> 5;
    int m0 = blockIdx.x * 128, n0 = blockIdx.y * 64;
    int seg = (m0 < ROW_SRC) ? 0 : (m0 < ROW_WORD) ? 1 : (m0 < ROW_WQW) ? 2 :
              (m0 < ROW_WQS) ? 3 : (m0 < ROW_WQP) ? 4 : 5;
    const __nv_bfloat16* BhSeg = g_BhG + (size_t)seg * DD * DD;
    const __nv_bfloat16* BlSeg = g_BlG + (size_t)seg * DD * DD;

    int gr = lane >> 2, gc = lane & 3;
    int quad = lane >> 3, lrow = lane & 7;
    int ldsm_half = ((quad & 1) * 8 + lrow) * BSTH + (quad >> 1) * 8;

    float acc[2][8][4];
#pragma unroll
    for (int mt = 0; mt < 2; mt++)
#pragma unroll
        for (int nt = 0; nt < 8; nt++)
#pragma unroll
            for (int c = 0; c < 4; c++) acc[mt][nt][c] = 0.0f;

    stage_chunk(sb, 0, 0, m0, n0, BhSeg, BlSeg, tid);
    CP_COMMIT();

    for (int kc = 0; kc < 16; kc++) {
        int st = kc & 1;
        if (kc < 15) {
            stage_chunk(sb, st ^ 1, kc + 1, m0, n0, BhSeg, BlSeg, tid);
            CP_COMMIT();
            CP_WAIT1();
        } else {
            CP_WAIT0();
        }
        __syncthreads();

#pragma unroll
        for (int step = 0; step < 2; step++) {
            int kkp = step * 8;
            int kk2 = step * 16;
            uint32_t ah[2][4], al[2][4];
#pragma unroll
            for (int mt = 0; mt < 2; mt++) {
                int mr = wid * 32 + mt * 16 + gr;
                ah[mt][0] = smU[OFF_AHI(st) + mr * APST + kkp + gc];
                ah[mt][1] = smU[OFF_AHI(st) + (mr + 8) * APST + kkp + gc];
                ah[mt][2] = smU[OFF_AHI(st) + mr * APST + kkp + gc + 4];
                ah[mt][3] = smU[OFF_AHI(st) + (mr + 8) * APST + kkp + gc + 4];
                al[mt][0] = smU[OFF_ALO(st) + mr * APST + kkp + gc];
                al[mt][1] = smU[OFF_ALO(st) + (mr + 8) * APST + kkp + gc];
                al[mt][2] = smU[OFF_ALO(st) + mr * APST + kkp + gc + 4];
                al[mt][3] = smU[OFF_ALO(st) + (mr + 8) * APST + kkp + gc + 4];
            }
#pragma unroll
            for (int np = 0; np < 4; np++) {
                uint32_t hoff = (uint32_t)((kk2 * BSTH + np * 16 + ldsm_half) * 2);
                uint32_t bh4[4], bl4[4];
                LDSM_X4_T(bh4, sb + 4 * OFF_BH(st) + hoff);
                LDSM_X4_T(bl4, sb + 4 * OFF_BL(st) + hoff);
#pragma unroll
                for (int sub = 0; sub < 2; sub++) {
#pragma unroll
                    for (int mt = 0; mt < 2; mt++) {
                        MMA_BF16(acc[mt][np * 2 + sub], ah[mt], &bh4[sub * 2]);
                        MMA_BF16(acc[mt][np * 2 + sub], ah[mt], &bl4[sub * 2]);
                        MMA_BF16(acc[mt][np * 2 + sub], al[mt], &bh4[sub * 2]);
                    }
                }
            }
        }
        __syncthreads();
    }

    const float* bias = (seg == 3) ? bqw : (seg == 4) ? bqs : (seg == 5) ? bqp : (const float*)0;
#pragma unroll
    for (int nt = 0; nt < 8; nt++) {
        int n = n0 + nt * 8 + gc * 2;
        float b0 = bias ? bias[n] : 0.0f;
        float b1 = bias ? bias[n + 1] : 0.0f;
#pragma unroll
        for (int mt = 0; mt < 2; mt++) {
            int m = m0 + wid * 32 + mt * 16 + gr;
            *(float2*)&g_act[(size_t)m * DD + n] =
                make_float2(acc[mt][nt][0] + b0, acc[mt][nt][1] + b1);
            *(float2*)&g_act[(size_t)(m + 8) * DD + n] =
                make_float2(acc[mt][nt][2] + b0, acc[mt][nt][3] + b1);
        }
    }
}

// ============================================================
// sentence-level scores
// ============================================================
__global__ __launch_bounds__(512) void sent_kernel(const float* __restrict__ v_sent)
{
    __shared__ float wq_s[DD];
    __shared__ float vs[DD];
    int row = blockIdx.x;
    int b = row / TD;
    int tid = threadIdx.x, lane = tid & 31, w = tid >> 5;
    wq_s[tid] = g_act[(size_t)(ROW_WQS + row) * DD + tid];
    vs[tid] = v_sent[tid];
    __syncthreads();
    const float* uh = g_act + (size_t)(b * 16 + w) * DD;
    float acc = 0.f;
#pragma unroll
    for (int it = 0; it < 4; it++) {
        int d = it * 128 + lane * 4;
        float4 u = *(const float4*)&uh[d];
        acc += vs[d + 0] * tanh_fast(wq_s[d + 0] + u.x);
        acc += vs[d + 1] * tanh_fast(wq_s[d + 1] + u.y);
        acc += vs[d + 2] * tanh_fast(wq_s[d + 2] + u.z);
        acc += vs[d + 3] * tanh_fast(wq_s[d + 3] + u.w);
    }
#pragma unroll
    for (int o = 16; o; o >>= 1) acc += __shfl_xor_sync(0xffffffffu, acc, o);
    if (lane == 0) g_sent[row * SENTN + w] = acc;
}

// ============================================================
// main score kernel: d split in QUARTERS (grid z = b + 4*q, 16)
// ============================================================
#define SC_CHUNK 64
#define SC_STRIDE 68
__global__ __launch_bounds__(256) void score_kernel(
    const float* __restrict__ v_pass, const float* __restrict__ v_word)
{
    __shared__ float wq_s[16 * SC_STRIDE];
    __shared__ float uh_s[80 * SC_STRIDE];
    __shared__ float v_s[SC_CHUNK];
    int tid = threadIdx.x;
    int jt = blockIdx.x, tt = blockIdx.y;
    int b = blockIdx.z & 3, quar = blockIdx.z >> 2;
    int t0 = tt * 16;
    bool is_src = (jt < 5);
    const float* wqb = g_act + (size_t)((is_src ? ROW_WQP : ROW_WQW) + b * TD) * DD;
    int uh0 = is_src ? (ROW_SRC + b * SRCN + jt * 80) : (ROW_WORD + b * 640 + (jt - 5) * 80);
    const float* v = is_src ? v_pass : v_word;
    int d_base = quar * 128;

    int tx = tid & 15, ty = tid >> 4;
    float acc[5] = {0.f, 0.f, 0.f, 0.f, 0.f};

    for (int c = 0; c < 2; c++) {
        int d0 = d_base + c * SC_CHUNK;
        __syncthreads();
        {
            int r = tid >> 4, col = (tid & 15) << 2;
            *(float4*)&wq_s[r * SC_STRIDE + col] =
                *(const float4*)&wqb[(size_t)(t0 + r) * DD + d0 + col];
        }
        for (int i = tid; i < 80 * 16; i += 256) {
            int r = i >> 4, col = (i & 15) << 2;
            *(float4*)&uh_s[r * SC_STRIDE + col] =
                *(const float4*)&g_act[(size_t)(uh0 + r) * DD + d0 + col];
        }
        if (tid < SC_CHUNK) v_s[tid] = v[d0 + tid];
        __syncthreads();
#pragma unroll 4
        for (int d4 = 0; d4 < 16; d4++) {
            float4 w4 = *(const float4*)&wq_s[ty * SC_STRIDE + (d4 << 2)];
            float4 v4 = *(const float4*)&v_s[d4 << 2];
#pragma unroll
            for (int u = 0; u < 5; u++) {
                float4 u4 = *(const float4*)&uh_s[(tx + 16 * u) * SC_STRIDE + (d4 << 2)];
                acc[u] += v4.x * tanh_fast(w4.x + u4.x);
                acc[u] += v4.y * tanh_fast(w4.y + u4.y);
                acc[u] += v4.z * tanh_fast(w4.z + u4.z);
                acc[u] += v4.w * tanh_fast(w4.w + u4.w);
            }
        }
    }

    int t = t0 + ty;
    if (t < TD) {
        float* arow = g_alignQ + (size_t)quar * BT * SJ + (size_t)(b * TD + t) * SJ;
        int jcol0 = is_src ? jt * 80 : SRCN + (jt - 5) * 80;
#pragma unroll
        for (int u = 0; u < 5; u++)
            arow[jcol0 + tx + 16 * u] = acc[u];
    }
}

// ============================================================
// softmax: combine quarters, hier multiply, mask, softmax
// ============================================================
__global__ __launch_bounds__(256) void softmax_kernel(
    const int* __restrict__ src_len, const int* __restrict__ word_len)
{
    __shared__ float sval[SJ];
    __shared__ float red[256];
    __shared__ float sents[SENTN];
    int row = blockIdx.x, tid = threadIdx.x;
    int b = row / TD;
    if (tid < SENTN) sents[tid] = g_sent[row * SENTN + tid];
    __syncthreads();
    int sl = src_len[b];
    for (int j = tid; j < SJ; j += 256) {
        size_t o = (size_t)row * SJ + j;
        float rv = g_alignQ[o] + g_alignQ[(size_t)BT * SJ + o]
                 + g_alignQ[2 * (size_t)BT * SJ + o] + g_alignQ[3 * (size_t)BT * SJ + o];
        float val;
        if (j < SRCN) {
            val = (j < sl) ? rv : -1e30f;
        } else {
            int jw = j - SRCN; int s = jw / WORDN, w = jw - s * WORDN;
            val = (w < word_len[b * SENTN + s]) ? rv * sents[s] : -1e30f;
        }
        sval[j] = val;
    }
    __syncthreads();
    float m = -3.4e38f;
    for (int j = tid; j < SJ; j += 256) m = fmaxf(m, sval[j]);
    red[tid] = m; __syncthreads();
    for (int o = 128; o; o >>= 1) { if (tid < o) red[tid] = fmaxf(red[tid], red[tid + o]); __syncthreads(); }
    m = red[0]; __syncthreads();
    float s = 0.f;
    for (int j = tid; j < SJ; j += 256) { float e = __expf(sval[j] - m); sval[j] = e; s += e; }
    red[tid] = s; __syncthreads();
    for (int o = 128; o; o >>= 1) { if (tid < o) red[tid] += red[tid + o]; __syncthreads(); }
    float inv = 1.0f / red[0];
    for (int j = tid; j < SJ; j += 256) g_p[(size_t)row * SJ + j] = sval[j] * inv;
}

// ============================================================
// context: c[b,t,d] = sum_j p[b,t,j] * mem[b,j,d]
// ============================================================
__global__ __launch_bounds__(256) void context_kernel(
    const float* __restrict__ srcb, const float* __restrict__ wordb, float* __restrict__ out)
{
    __shared__ float p_s[50 * 80];
    __shared__ float m_s[80 * 33];
    int tid = threadIdx.x;
    int b = blockIdx.y;
    int d0 = blockIdx.x * 32;
    int tx = tid & 31, ty = tid >> 5;
    float acc[7] = {};

    for (int j0 = 0; j0 < SJ; j0 += 80) {
        __syncthreads();
        for (int i = tid; i < 50 * 80; i += 256) {
            int r = i / 80, c = i - r * 80;
            p_s[i] = g_p[(size_t)(b * TD + r) * SJ + j0 + c];
        }
        for (int i = tid; i < 80 * 32; i += 256) {
            int r = i >> 5, c = i & 31;
            int j = j0 + r;
            const float* mp;
            if (j < SRCN) mp = srcb + (size_t)(j * BD + b) * DD;
            else { int jw = j - SRCN; int s = jw / WORDN, w = jw - s * WORDN;
                   mp = wordb + (size_t)((w * BD + b) * SENTN + s) * DD; }
            m_s[r * 33 + c] = mp[d0 + c];
        }
        __syncthreads();
        for (int j = 0; j < 80; j++) {
            float mv = m_s[j * 33 + tx];
#pragma unroll
            for (int q = 0; q < 7; q++) {
                int t = ty + (q << 3);
                if (t < TD) acc[q] += p_s[t * 80 + j] * mv;
            }
        }
    }
#pragma unroll
    for (int q = 0; q < 7; q++) {
        int t = ty + (q << 3);
        if (t < TD) out[(size_t)(b * TD + t) * DD + d0 + tx] = acc[q];
    }
}

// ============================================================
extern "C" void kernel_launch(void* const* d_in, const int* in_sizes, int n_in,
                              void* d_out, int out_size)
{
    const float* source    = (const float*)d_in[0];
    const float* src_bank  = (const float*)d_in[1];
    const int*   src_len   = (const int*)  d_in[2];
    const float* sent_bank = (const float*)d_in[3];
    const float* word_bank = (const float*)d_in[5];
    const int*   word_len  = (const int*)  d_in[6];
    const float* Wq_word = (const float*)d_in[7];
    const float* bq_word = (const float*)d_in[8];
    const float* Uc_word = (const float*)d_in[9];
    const float* v_word  = (const float*)d_in[10];
    const float* Wq_sent = (const float*)d_in[11];
    const float* bq_sent = (const float*)d_in[12];
    const float* Uc_sent = (const float*)d_in[13];
    const float* v_sent  = (const float*)d_in[14];
    const float* Wq_pass = (const float*)d_in[15];
    const float* bq_pass = (const float*)d_in[16];
    const float* Uc_pass = (const float*)d_in[17];
    const float* v_pass  = (const float*)d_in[18];
    float* out = (float*)d_out;

    cudaFuncSetAttribute(bf16_gemm, cudaFuncAttributeMaxDynamicSharedMemorySize, SMEM_BYTES);

    conv_a<<<MROWS, 128>>>(sent_bank, src_bank, word_bank, source);
    conv_b<<<6 * 512, 128>>>(Uc_sent, Uc_pass, Uc_word, Wq_word, Wq_sent, Wq_pass);
    bf16_gemm<<<dim3(40, 8), 128, SMEM_BYTES>>>(bq_word, bq_sent, bq_pass);
    sent_kernel<<<200, 512>>>(v_sent);
    score_kernel<<<dim3(13, 4, 16), 256>>>(v_pass, v_word);
    softmax_kernel<<<200, 256>>>(src_len, word_len);
    context_kernel<<<dim3(16, 4), 256>>>(src_bank, word_bank, out);
}